// round 12
// baseline (speedup 1.0000x reference)
#include <cuda_runtime.h>
#include <cuda_fp16.h>
#include <math.h>
#include <stdint.h>

// Problem constants
#define B_  4
#define T_  2048
#define H_  16
#define D_  64
#define C_  1024
#define FF_ 4096
#define M_  (B_ * T_)   // 8192 rows

// ---------------------------------------------------------------------------
// Scratch (device globals — no runtime allocation allowed)
// ---------------------------------------------------------------------------
__device__ __half g_xn  [M_ * C_];        // LN output (fp16, GEMM A-side)
__device__ __half g_qkv [M_ * 3 * C_];    // qkv projections (fp16)
__device__ __half g_y   [M_ * C_];        // attention output (fp16)
__device__ float  g_x1  [M_ * C_];        // first residual (fp32)
__device__ __half g_h   [M_ * FF_];       // gelu(fc) activations (fp16)
// fp16 k-pair-interleaved weights: element (k,n) at  (k>>1)*2N + 2n + (k&1)
__device__ __half g_wqkv[C_ * 3 * C_];
__device__ __half g_wo  [C_ * C_];
__device__ __half g_wfc [C_ * FF_];
__device__ __half g_wout[FF_ * C_];

// ---------------------------------------------------------------------------
// Helpers
// ---------------------------------------------------------------------------
__device__ __forceinline__ uint32_t f2tf32(float f) {
    uint32_t r;
    asm("cvt.rna.tf32.f32 %0, %1;" : "=r"(r) : "f"(f));
    return r;
}
__device__ __forceinline__ float tf32_round(float f) {
    return __uint_as_float(f2tf32(f));
}

// f32-accumulator fp16 mma
__device__ __forceinline__ void mma_f16(
    float& d0, float& d1, float& d2, float& d3,
    uint32_t a0, uint32_t a1, uint32_t a2, uint32_t a3,
    uint32_t b0, uint32_t b1)
{
    asm volatile(
        "mma.sync.aligned.m16n8k16.row.col.f32.f16.f16.f32 "
        "{%0,%1,%2,%3}, {%4,%5,%6,%7}, {%8,%9}, {%0,%1,%2,%3};\n"
        : "+f"(d0), "+f"(d1), "+f"(d2), "+f"(d3)
        : "r"(a0), "r"(a1), "r"(a2), "r"(a3), "r"(b0), "r"(b1));
}

__device__ __forceinline__ void ldmx4t(
    uint32_t& d0, uint32_t& d1, uint32_t& d2, uint32_t& d3, uint32_t addr)
{
    asm volatile(
        "ldmatrix.sync.aligned.m8n8.x4.trans.shared.b16 {%0,%1,%2,%3}, [%4];"
        : "=r"(d0), "=r"(d1), "=r"(d2), "=r"(d3) : "r"(addr));
}

__device__ __forceinline__ void cp_async16(void* dst_smem, const void* src) {
    uint32_t d = (uint32_t)__cvta_generic_to_shared(dst_smem);
    asm volatile("cp.async.cg.shared.global [%0], [%1], 16;\n" :: "r"(d), "l"(src));
}
__device__ __forceinline__ void cp_commit() {
    asm volatile("cp.async.commit_group;\n");
}
template<int N>
__device__ __forceinline__ void cp_wait() {
    asm volatile("cp.async.wait_group %0;\n" :: "n"(N));
}

__device__ __forceinline__ float gelu_exact(float x) {
    return 0.5f * x * (1.0f + erff(x * 0.70710678118654752f));
}

// ---------------------------------------------------------------------------
// Fused weight prep: all 4 weights, fp32 [K][N] -> fp16 interleaved
// [K/2][N][2]. Flat chunk index; 1 chunk = 8 output halves (2k x 4n).
// ---------------------------------------------------------------------------
__device__ __forceinline__ void wprep_chunk(
    const float* __restrict__ src, __half* __restrict__ dst, int N, int idx)
{
    const int nq = N >> 2;
    const int kp = idx / nq;
    const int n4 = idx - kp * nq;
    const float4 r0 = *(const float4*)(src + (size_t)(2 * kp)     * N + 4 * n4);
    const float4 r1 = *(const float4*)(src + (size_t)(2 * kp + 1) * N + 4 * n4);
    __half2* d = (__half2*)(dst + (size_t)kp * (2 * N) + 8 * n4);
    d[0] = __halves2half2(__float2half_rn(r0.x), __float2half_rn(r1.x));
    d[1] = __halves2half2(__float2half_rn(r0.y), __float2half_rn(r1.y));
    d[2] = __halves2half2(__float2half_rn(r0.z), __float2half_rn(r1.z));
    d[3] = __halves2half2(__float2half_rn(r0.w), __float2half_rn(r1.w));
}

// chunk counts: qkv 393216 | wo 131072 | wfc 524288 | wout 524288
#define WCH0 393216
#define WCH1 (WCH0 + 131072)
#define WCH2 (WCH1 + 524288)
#define WCH3 (WCH2 + 524288)   // 1572864 total

__global__ void __launch_bounds__(256) wprep_all_kernel(
    const float* __restrict__ s0, __half* __restrict__ d0,
    const float* __restrict__ s1, __half* __restrict__ d1,
    const float* __restrict__ s2, __half* __restrict__ d2,
    const float* __restrict__ s3, __half* __restrict__ d3)
{
    #pragma unroll
    for (int u = 0; u < 2; u++) {
        const int g = (blockIdx.x * 2 + u) * 256 + threadIdx.x;
        if (g >= WCH3) return;
        if      (g < WCH0) wprep_chunk(s0, d0, 3 * C_, g);
        else if (g < WCH1) wprep_chunk(s1, d1, C_,     g - WCH0);
        else if (g < WCH2) wprep_chunk(s2, d2, FF_,    g - WCH1);
        else               wprep_chunk(s3, d3, C_,     g - WCH2);
    }
}

// ---------------------------------------------------------------------------
// LayerNorm: warp-per-row (8 rows per 256-thread CTA), pure shuffle
// reduction, no smem/syncthreads. Outputs fp16.
// ---------------------------------------------------------------------------
__global__ void __launch_bounds__(256) ln_kernel(
    const float* __restrict__ x, const float* __restrict__ w,
    const float* __restrict__ b, __half* __restrict__ out)
{
    const int lane = threadIdx.x & 31;
    const int row  = blockIdx.x * 8 + (threadIdx.x >> 5);
    const float4* xp = (const float4*)(x + (size_t)row * C_);

    float4 v[8];
    float s = 0.f, s2 = 0.f;
    #pragma unroll
    for (int i = 0; i < 8; i++) {
        v[i] = xp[lane + 32 * i];
        s  += v[i].x + v[i].y + v[i].z + v[i].w;
        s2 += v[i].x*v[i].x + v[i].y*v[i].y + v[i].z*v[i].z + v[i].w*v[i].w;
    }
    #pragma unroll
    for (int o = 16; o > 0; o >>= 1) {
        s  += __shfl_xor_sync(0xffffffffu, s,  o);
        s2 += __shfl_xor_sync(0xffffffffu, s2, o);
    }
    const float mean = s * (1.0f / C_);
    const float var  = s2 * (1.0f / C_) - mean * mean;
    const float rstd = rsqrtf(var + 1e-5f);

    uint2* op = (uint2*)(out + (size_t)row * C_);
    #pragma unroll
    for (int i = 0; i < 8; i++) {
        const float4 wv = ((const float4*)w)[lane + 32 * i];
        const float4 bv = ((const float4*)b)[lane + 32 * i];
        __half2 h0 = __halves2half2(
            __float2half_rn((v[i].x - mean) * rstd * wv.x + bv.x),
            __float2half_rn((v[i].y - mean) * rstd * wv.y + bv.y));
        __half2 h1 = __halves2half2(
            __float2half_rn((v[i].z - mean) * rstd * wv.z + bv.z),
            __float2half_rn((v[i].w - mean) * rstd * wv.w + bv.w));
        uint2 u;
        u.x = *(uint32_t*)&h0;
        u.y = *(uint32_t*)&h1;
        op[lane + 32 * i] = u;
    }
}

// ---------------------------------------------------------------------------
// FP16 tensor-core GEMM (f32 accumulators), templated CTA width.
// CTA 128 x BN_T x 32, 8 warps (2x4) of 64 x BN_T/4, mma.m16n8k16,
// 3-stage cp.async. OUT: 0 = f32, 1 = f32 tf32-rounded, 2 = f16.
// BN_T in {128, 96}; B_STR = 2*BN_T+16 keeps frag-load banks conflict-free
// ( (2*BN_T+16)*2/4 mod 32 == 8 for both ).
// ---------------------------------------------------------------------------
#define BM 128
#define BK 32
#define STAGES 3
#define A_STR 40
#define A_TILE_H (BM * A_STR)          // 5120 halves

template<int BN_T> struct GemmCfg {
    static const int B_STR    = 2 * BN_T + 16;
    static const int B_TILE_H = 16 * B_STR;
    static const int NFRAG    = BN_T / 32;
    static const int WN       = BN_T / 4;            // warp col width
    static const int BCHUNKS  = 16 * (BN_T / 4);     // 16B chunks per B tile
    static const int SMEM     = STAGES * (A_TILE_H + B_TILE_H) * 2;
};
// BN=128: B_STR=272, SMEM=56832 | BN=96: B_STR=208, SMEM=50688

template<int BN_T, int ACT, int RES, int OUT>
__global__ void __launch_bounds__(256) gemm_h_kernel(
    const __half* __restrict__ A, const __half* __restrict__ Wp,
    const float* __restrict__ bias, const float* __restrict__ res,
    void* __restrict__ outv, int M, int N, int K)
{
    typedef GemmCfg<BN_T> CFG;
    extern __shared__ __half hsm[];
    __half* As = hsm;
    __half* Bs = hsm + STAGES * A_TILE_H;

    const int tid  = threadIdx.x;
    const int lane = tid & 31;
    const int wid  = tid >> 5;
    const int wm   = wid >> 2;
    const int wn   = wid & 3;
    const int bm   = blockIdx.y;
    const int bn   = blockIdx.x;
    const int fr   = lane >> 2;
    const int fc   = lane & 3;

    float acc[4][CFG::NFRAG][4];
    #pragma unroll
    for (int i = 0; i < 4; i++)
        #pragma unroll
        for (int j = 0; j < CFG::NFRAG; j++)
            #pragma unroll
            for (int r = 0; r < 4; r++) acc[i][j][r] = 0.f;

    const int ntiles = K / BK;

    auto load_tile = [&](int t, int stg) {
        const int k0 = t * BK;
        __half* Ab = As + stg * A_TILE_H;
        __half* Bb = Bs + stg * CFG::B_TILE_H;
        #pragma unroll
        for (int i = 0; i < 2; i++) {
            const int idx = i * 256 + tid;
            const int row = idx >> 2, c4 = idx & 3;
            cp_async16(Ab + row * A_STR + c4 * 8,
                       A + (size_t)(bm * BM + row) * K + k0 + c4 * 8);
        }
        const int kp0 = k0 >> 1;
        const int cpr = BN_T / 4;          // chunks per kp-row
        #pragma unroll
        for (int i = 0; i < 2; i++) {
            const int idx = i * 256 + tid;
            if (BN_T == 128 || idx < CFG::BCHUNKS) {
                const int kp = idx / cpr, ch = idx % cpr;
                cp_async16(Bb + kp * CFG::B_STR + ch * 8,
                           Wp + (size_t)(kp0 + kp) * (2 * N) + (size_t)bn * (2 * BN_T) + ch * 8);
            }
        }
        cp_commit();
    };

    load_tile(0, 0);
    load_tile(1, 1);

    for (int t = 0; t < ntiles; t++) {
        if (t + 2 < ntiles) load_tile(t + 2, (t + 2) % STAGES);
        else                cp_commit();
        cp_wait<2>();
        __syncthreads();

        const __half* Ab = As + (t % STAGES) * A_TILE_H;
        const __half* Bb = Bs + (t % STAGES) * CFG::B_TILE_H;

        #pragma unroll
        for (int ks = 0; ks < 2; ks++) {
            const int kc = ks * 16;
            uint32_t af[4][4], bf[CFG::NFRAG][2];
            #pragma unroll
            for (int mi = 0; mi < 4; mi++) {
                const int base = (wm * 64 + mi * 16 + fr) * A_STR + kc + 2 * fc;
                af[mi][0] = *(const uint32_t*)&Ab[base];
                af[mi][1] = *(const uint32_t*)&Ab[base + 8 * A_STR];
                af[mi][2] = *(const uint32_t*)&Ab[base + 8];
                af[mi][3] = *(const uint32_t*)&Ab[base + 8 * A_STR + 8];
            }
            const int kp = ks * 8 + fc;
            #pragma unroll
            for (int ni = 0; ni < CFG::NFRAG; ni++) {
                const int n2 = 2 * (wn * CFG::WN + ni * 8 + fr);
                bf[ni][0] = *(const uint32_t*)&Bb[kp * CFG::B_STR + n2];
                bf[ni][1] = *(const uint32_t*)&Bb[(kp + 4) * CFG::B_STR + n2];
            }
            #pragma unroll
            for (int mi = 0; mi < 4; mi++)
                #pragma unroll
                for (int ni = 0; ni < CFG::NFRAG; ni++)
                    mma_f16(acc[mi][ni][0], acc[mi][ni][1],
                            acc[mi][ni][2], acc[mi][ni][3],
                            af[mi][0], af[mi][1], af[mi][2], af[mi][3],
                            bf[ni][0], bf[ni][1]);
        }
        __syncthreads();
    }

    // ---- epilogue ----
    #pragma unroll
    for (int mi = 0; mi < 4; mi++) {
        const int row0 = bm * BM + wm * 64 + mi * 16 + fr;
        #pragma unroll
        for (int ni = 0; ni < CFG::NFRAG; ni++) {
            const int col = bn * BN_T + wn * CFG::WN + ni * 8 + fc * 2;
            const float b0 = bias[col], b1 = bias[col + 1];

            float v0 = acc[mi][ni][0] + b0;
            float v1 = acc[mi][ni][1] + b1;
            float v2 = acc[mi][ni][2] + b0;
            float v3 = acc[mi][ni][3] + b1;
            if (ACT == 1) {
                v0 = gelu_exact(v0); v1 = gelu_exact(v1);
                v2 = gelu_exact(v2); v3 = gelu_exact(v3);
            }
            if (RES) {
                const float2 r0 = *(const float2*)(res + (size_t)row0 * N + col);
                const float2 r1 = *(const float2*)(res + (size_t)(row0 + 8) * N + col);
                v0 += r0.x; v1 += r0.y; v2 += r1.x; v3 += r1.y;
            }
            if (OUT == 2) {
                __half* out = (__half*)outv;
                *(__half2*)(out + (size_t)row0 * N + col) =
                    __halves2half2(__float2half_rn(v0), __float2half_rn(v1));
                *(__half2*)(out + (size_t)(row0 + 8) * N + col) =
                    __halves2half2(__float2half_rn(v2), __float2half_rn(v3));
            } else {
                if (OUT == 1) {
                    v0 = tf32_round(v0); v1 = tf32_round(v1);
                    v2 = tf32_round(v2); v3 = tf32_round(v3);
                }
                float* out = (float*)outv;
                *(float2*)(out + (size_t)row0 * N + col)       = make_float2(v0, v1);
                *(float2*)(out + (size_t)(row0 + 8) * N + col) = make_float2(v2, v3);
            }
        }
    }
}

// ---------------------------------------------------------------------------
// FP16 tensor-core causal flash attention (R9 kernel, unchanged).
// ---------------------------------------------------------------------------
#define HS 72
#define QH (64 * HS)
#define ATTN_SMEM_BYTES ((QH * 6) * 2)    // Q + 2K + 2V + P = 55296 B

__global__ void __launch_bounds__(128) attn_h_kernel(
    const __half* __restrict__ qkv, __half* __restrict__ y)
{
    extern __shared__ __half asm_[];
    __half* Qs = asm_;
    __half* Ks = Qs + QH;          // 2 buffers
    __half* Vs = Ks + 2 * QH;      // 2 buffers
    __half* Ps = Vs + 2 * QH;

    const int qt   = blockIdx.x;
    const int h    = blockIdx.y;
    const int b    = blockIdx.z;
    const int tid  = threadIdx.x;
    const int lane = tid & 31;
    const int w    = tid >> 5;
    const int fr   = lane >> 2;
    const int fc   = lane & 3;

    const size_t base = (size_t)(b * T_) * (3 * C_) + h * D_;

    {
        #pragma unroll
        for (int i = 0; i < 4; i++) {
            const int idx = i * 128 + tid;
            const int r = idx >> 3, ch = idx & 7;
            cp_async16(Qs + r * HS + ch * 8,
                       qkv + base + (size_t)(qt * 64 + r) * (3 * C_) + ch * 8);
        }
        #pragma unroll
        for (int i = 0; i < 4; i++) {
            const int idx = i * 128 + tid;
            const int r = idx >> 3, ch = idx & 7;
            const __half* src = qkv + base + (size_t)r * (3 * C_) + ch * 8;
            cp_async16(Ks + r * HS + ch * 8, src + C_);
            cp_async16(Vs + r * HS + ch * 8, src + 2 * C_);
        }
        cp_commit();
    }

    auto load_kv = [&](int kt, int bufi) {
        __half* Kb = Ks + bufi * QH;
        __half* Vb = Vs + bufi * QH;
        #pragma unroll
        for (int i = 0; i < 4; i++) {
            const int idx = i * 128 + tid;
            const int r = idx >> 3, ch = idx & 7;
            const __half* src = qkv + base + (size_t)(kt * 64 + r) * (3 * C_) + ch * 8;
            cp_async16(Kb + r * HS + ch * 8, src + C_);
            cp_async16(Vb + r * HS + ch * 8, src + 2 * C_);
        }
        cp_commit();
    };

    float accO[8][4];
    #pragma unroll
    for (int ni = 0; ni < 8; ni++)
        #pragma unroll
        for (int r = 0; r < 4; r++) accO[ni][r] = 0.f;
    float m0 = -INFINITY, m1 = -INFINITY, l0 = 0.f, l1 = 0.f;

    __half* Ps_w = Ps + w * 16 * HS;
    const int rlo = w * 16 + fr;

    int buf = 0;
    for (int kt = 0; kt <= qt; kt++) {
        if (kt < qt) { load_kv(kt + 1, buf ^ 1); cp_wait<1>(); }
        else         { cp_wait<0>(); }
        __syncthreads();

        const __half* Kb = Ks + buf * QH;
        const __half* Vb = Vs + buf * QH;

        float accS[8][4];
        #pragma unroll
        for (int ni = 0; ni < 8; ni++)
            #pragma unroll
            for (int r = 0; r < 4; r++) accS[ni][r] = 0.f;

        #pragma unroll
        for (int ks = 0; ks < 4; ks++) {
            const int kc = ks * 16;
            const uint32_t a0 = *(const uint32_t*)&Qs[(rlo    ) * HS + kc + 2*fc];
            const uint32_t a1 = *(const uint32_t*)&Qs[(rlo + 8) * HS + kc + 2*fc];
            const uint32_t a2 = *(const uint32_t*)&Qs[(rlo    ) * HS + kc + 8 + 2*fc];
            const uint32_t a3 = *(const uint32_t*)&Qs[(rlo + 8) * HS + kc + 8 + 2*fc];
            #pragma unroll
            for (int ni = 0; ni < 8; ni++) {
                const uint32_t b0 = *(const uint32_t*)&Kb[(ni*8 + fr) * HS + kc + 2*fc];
                const uint32_t b1 = *(const uint32_t*)&Kb[(ni*8 + fr) * HS + kc + 8 + 2*fc];
                mma_f16(accS[ni][0], accS[ni][1], accS[ni][2], accS[ni][3],
                        a0, a1, a2, a3, b0, b1);
            }
        }

        const bool diag = (kt == qt);
        float mx0 = -INFINITY, mx1 = -INFINITY;
        #pragma unroll
        for (int ni = 0; ni < 8; ni++) {
            float s0 = accS[ni][0] * 0.125f;
            float s1 = accS[ni][1] * 0.125f;
            float s2 = accS[ni][2] * 0.125f;
            float s3 = accS[ni][3] * 0.125f;
            if (diag) {
                const int j = ni * 8 + 2 * fc;
                if (j     > rlo    ) s0 = -INFINITY;
                if (j + 1 > rlo    ) s1 = -INFINITY;
                if (j     > rlo + 8) s2 = -INFINITY;
                if (j + 1 > rlo + 8) s3 = -INFINITY;
            }
            accS[ni][0] = s0; accS[ni][1] = s1;
            accS[ni][2] = s2; accS[ni][3] = s3;
            mx0 = fmaxf(mx0, fmaxf(s0, s1));
            mx1 = fmaxf(mx1, fmaxf(s2, s3));
        }
        mx0 = fmaxf(mx0, __shfl_xor_sync(0xffffffffu, mx0, 1));
        mx0 = fmaxf(mx0, __shfl_xor_sync(0xffffffffu, mx0, 2));
        mx1 = fmaxf(mx1, __shfl_xor_sync(0xffffffffu, mx1, 1));
        mx1 = fmaxf(mx1, __shfl_xor_sync(0xffffffffu, mx1, 2));

        const float mn0 = fmaxf(m0, mx0);
        const float mn1 = fmaxf(m1, mx1);
        const float c0 = __expf(m0 - mn0);
        const float c1 = __expf(m1 - mn1);

        float ls0 = 0.f, ls1 = 0.f;
        #pragma unroll
        for (int ni = 0; ni < 8; ni++) {
            const float p0 = __expf(accS[ni][0] - mn0);
            const float p1 = __expf(accS[ni][1] - mn0);
            const float p2 = __expf(accS[ni][2] - mn1);
            const float p3 = __expf(accS[ni][3] - mn1);
            ls0 += p0 + p1;  ls1 += p2 + p3;
            accO[ni][0] *= c0; accO[ni][1] *= c0;
            accO[ni][2] *= c1; accO[ni][3] *= c1;
            const int colp = ni * 8 + 2 * fc;
            *(__half2*)&Ps_w[(fr    ) * HS + colp] =
                __halves2half2(__float2half_rn(p0), __float2half_rn(p1));
            *(__half2*)&Ps_w[(fr + 8) * HS + colp] =
                __halves2half2(__float2half_rn(p2), __float2half_rn(p3));
        }
        ls0 += __shfl_xor_sync(0xffffffffu, ls0, 1);
        ls0 += __shfl_xor_sync(0xffffffffu, ls0, 2);
        ls1 += __shfl_xor_sync(0xffffffffu, ls1, 1);
        ls1 += __shfl_xor_sync(0xffffffffu, ls1, 2);
        l0 = l0 * c0 + ls0;
        l1 = l1 * c1 + ls1;
        m0 = mn0; m1 = mn1;

        __syncwarp();

        const uint32_t vbase = (uint32_t)__cvta_generic_to_shared(Vb);
        const int mat = lane >> 3, rin = lane & 7;
        #pragma unroll
        for (int ks = 0; ks < 4; ks++) {
            const int kc = ks * 16;
            const uint32_t a0 = *(const uint32_t*)&Ps_w[(fr    ) * HS + kc + 2*fc];
            const uint32_t a1 = *(const uint32_t*)&Ps_w[(fr + 8) * HS + kc + 2*fc];
            const uint32_t a2 = *(const uint32_t*)&Ps_w[(fr    ) * HS + kc + 8 + 2*fc];
            const uint32_t a3 = *(const uint32_t*)&Ps_w[(fr + 8) * HS + kc + 8 + 2*fc];
            #pragma unroll
            for (int np = 0; np < 4; np++) {
                const int ni  = 2 * np;
                const int row = kc + ((mat & 1) ? 8 : 0) + rin;
                const int col = ni * 8 + ((mat & 2) ? 8 : 0);
                uint32_t b0, b1, b2, b3;
                ldmx4t(b0, b1, b2, b3, vbase + (uint32_t)(row * HS + col) * 2);
                mma_f16(accO[ni][0], accO[ni][1], accO[ni][2], accO[ni][3],
                        a0, a1, a2, a3, b0, b1);
                mma_f16(accO[ni+1][0], accO[ni+1][1], accO[ni+1][2], accO[ni+1][3],
                        a0, a1, a2, a3, b2, b3);
            }
        }

        __syncthreads();
        buf ^= 1;
    }

    const float inv0 = 1.f / l0;
    const float inv1 = 1.f / l1;
    const size_t grow = (size_t)(b * T_ + qt * 64 + rlo);
    #pragma unroll
    for (int ni = 0; ni < 8; ni++) {
        const int col = h * D_ + ni * 8 + 2 * fc;
        *(__half2*)(y + grow * C_ + col) =
            __halves2half2(__float2half_rn(accO[ni][0] * inv0),
                           __float2half_rn(accO[ni][1] * inv0));
        *(__half2*)(y + (grow + 8) * C_ + col) =
            __halves2half2(__float2half_rn(accO[ni][2] * inv1),
                           __float2half_rn(accO[ni][3] * inv1));
    }
}

// ---------------------------------------------------------------------------
// Launch
// ---------------------------------------------------------------------------
extern "C" void kernel_launch(void* const* d_in, const int* in_sizes, int n_in,
                              void* d_out, int out_size)
{
    (void)in_sizes; (void)n_in; (void)out_size;
    const float* x     = (const float*)d_in[0];
    const float* ln1_w = (const float*)d_in[1];
    const float* ln1_b = (const float*)d_in[2];
    const float* w_qkv = (const float*)d_in[3];
    const float* b_qkv = (const float*)d_in[4];
    const float* w_o   = (const float*)d_in[5];
    const float* b_o   = (const float*)d_in[6];
    const float* ln2_w = (const float*)d_in[7];
    const float* ln2_b = (const float*)d_in[8];
    const float* w_fc  = (const float*)d_in[9];
    const float* b_fc  = (const float*)d_in[10];
    const float* w_out = (const float*)d_in[11];
    const float* b_out = (const float*)d_in[12];
    float* out = (float*)d_out;

    __half *xn, *qkv, *y, *hbuf, *wq, *wo, *wf, *wu;
    float *x1;
    cudaGetSymbolAddress((void**)&xn,   g_xn);
    cudaGetSymbolAddress((void**)&qkv,  g_qkv);
    cudaGetSymbolAddress((void**)&y,    g_y);
    cudaGetSymbolAddress((void**)&x1,   g_x1);
    cudaGetSymbolAddress((void**)&hbuf, g_h);
    cudaGetSymbolAddress((void**)&wq,   g_wqkv);
    cudaGetSymbolAddress((void**)&wo,   g_wo);
    cudaGetSymbolAddress((void**)&wf,   g_wfc);
    cudaGetSymbolAddress((void**)&wu,   g_wout);

    const int SMEM128 = GemmCfg<128>::SMEM;   // 56832
    const int SMEM96  = GemmCfg<96>::SMEM;    // 50688

    cudaFuncSetAttribute(gemm_h_kernel<96,0,0,2>,
        cudaFuncAttributeMaxDynamicSharedMemorySize, SMEM96);
    cudaFuncSetAttribute(gemm_h_kernel<128,0,1,0>,
        cudaFuncAttributeMaxDynamicSharedMemorySize, SMEM128);
    cudaFuncSetAttribute(gemm_h_kernel<128,1,0,2>,
        cudaFuncAttributeMaxDynamicSharedMemorySize, SMEM128);
    cudaFuncSetAttribute(attn_h_kernel,
        cudaFuncAttributeMaxDynamicSharedMemorySize, ATTN_SMEM_BYTES);

    // 0) fused weight prep (all 4 weights, one launch)
    wprep_all_kernel<<<WCH3 / 512, 256>>>(
        w_qkv, wq, w_o, wo, w_fc, wf, w_out, wu);

    // 1) LN1 -> fp16
    ln_kernel<<<M_ / 8, 256>>>(x, ln1_w, ln1_b, xn);
    // 2) qkv = xn @ w_qkv + b_qkv  -> fp16   (BN=96: 2048 CTAs = 6.92 waves)
    gemm_h_kernel<96,0,0,2><<<dim3(3 * C_ / 96, M_ / BM), 256, SMEM96>>>(
        xn, wq, b_qkv, nullptr, qkv, M_, 3 * C_, C_);
    // 3) causal attention (fp16) -> y (fp16)
    attn_h_kernel<<<dim3(T_ / 64, H_, B_), 128, ATTN_SMEM_BYTES>>>(qkv, y);
    // 4) x1 = x + y @ w_o + b_o (fp32)
    gemm_h_kernel<128,0,1,0><<<dim3(C_ / 128, M_ / BM), 256, SMEM128>>>(
        y, wo, b_o, x, x1, M_, C_, C_);
    // 5) LN2 -> fp16
    ln_kernel<<<M_ / 8, 256>>>(x1, ln2_w, ln2_b, xn);
    // 6) h = gelu(xn @ w_fc + b_fc) -> fp16
    gemm_h_kernel<128,1,0,2><<<dim3(FF_ / 128, M_ / BM), 256, SMEM128>>>(
        xn, wf, b_fc, nullptr, hbuf, M_, FF_, C_);
    // 7) out = x1 + h @ w_out + b_out (fp32)
    gemm_h_kernel<128,0,1,0><<<dim3(C_ / 128, M_ / BM), 256, SMEM128>>>(
        hbuf, wu, b_out, x1, out, M_, C_, FF_);
}

// round 13
// speedup vs baseline: 1.0153x; 1.0153x over previous
#include <cuda_runtime.h>
#include <cuda_fp16.h>
#include <math.h>
#include <stdint.h>

// Problem constants
#define B_  4
#define T_  2048
#define H_  16
#define D_  64
#define C_  1024
#define FF_ 4096
#define M_  (B_ * T_)   // 8192 rows

// ---------------------------------------------------------------------------
// Scratch (device globals — no runtime allocation allowed)
// ---------------------------------------------------------------------------
__device__ __half g_xn  [M_ * C_];
__device__ __half g_qkv [M_ * 3 * C_];
__device__ __half g_y   [M_ * C_];
__device__ float  g_x1  [M_ * C_];
__device__ __half g_h   [M_ * FF_];
__device__ __half g_wqkv[C_ * 3 * C_];
__device__ __half g_wo  [C_ * C_];
__device__ __half g_wfc [C_ * FF_];
__device__ __half g_wout[FF_ * C_];

// ---------------------------------------------------------------------------
// Helpers
// ---------------------------------------------------------------------------
__device__ __forceinline__ uint32_t f2tf32(float f) {
    uint32_t r;
    asm("cvt.rna.tf32.f32 %0, %1;" : "=r"(r) : "f"(f));
    return r;
}
__device__ __forceinline__ float tf32_round(float f) {
    return __uint_as_float(f2tf32(f));
}

__device__ __forceinline__ void mma_f16(
    float& d0, float& d1, float& d2, float& d3,
    uint32_t a0, uint32_t a1, uint32_t a2, uint32_t a3,
    uint32_t b0, uint32_t b1)
{
    asm volatile(
        "mma.sync.aligned.m16n8k16.row.col.f32.f16.f16.f32 "
        "{%0,%1,%2,%3}, {%4,%5,%6,%7}, {%8,%9}, {%0,%1,%2,%3};\n"
        : "+f"(d0), "+f"(d1), "+f"(d2), "+f"(d3)
        : "r"(a0), "r"(a1), "r"(a2), "r"(a3), "r"(b0), "r"(b1));
}

__device__ __forceinline__ void ldmx4t(
    uint32_t& d0, uint32_t& d1, uint32_t& d2, uint32_t& d3, uint32_t addr)
{
    asm volatile(
        "ldmatrix.sync.aligned.m8n8.x4.trans.shared.b16 {%0,%1,%2,%3}, [%4];"
        : "=r"(d0), "=r"(d1), "=r"(d2), "=r"(d3) : "r"(addr));
}

__device__ __forceinline__ void cp_async16(void* dst_smem, const void* src) {
    uint32_t d = (uint32_t)__cvta_generic_to_shared(dst_smem);
    asm volatile("cp.async.cg.shared.global [%0], [%1], 16;\n" :: "r"(d), "l"(src));
}
__device__ __forceinline__ void cp_commit() {
    asm volatile("cp.async.commit_group;\n");
}
template<int N>
__device__ __forceinline__ void cp_wait() {
    asm volatile("cp.async.wait_group %0;\n" :: "n"(N));
}

__device__ __forceinline__ float gelu_exact(float x) {
    return 0.5f * x * (1.0f + erff(x * 0.70710678118654752f));
}
__device__ __forceinline__ uint32_t packh2(float a, float b) {
    __half2 h = __halves2half2(__float2half_rn(a), __float2half_rn(b));
    return *(uint32_t*)&h;
}

// ---------------------------------------------------------------------------
// Fused weight prep: all 4 weights, fp32 [K][N] -> fp16 interleaved
// ---------------------------------------------------------------------------
__device__ __forceinline__ void wprep_chunk(
    const float* __restrict__ src, __half* __restrict__ dst, int N, int idx)
{
    const int nq = N >> 2;
    const int kp = idx / nq;
    const int n4 = idx - kp * nq;
    const float4 r0 = *(const float4*)(src + (size_t)(2 * kp)     * N + 4 * n4);
    const float4 r1 = *(const float4*)(src + (size_t)(2 * kp + 1) * N + 4 * n4);
    __half2* d = (__half2*)(dst + (size_t)kp * (2 * N) + 8 * n4);
    d[0] = __halves2half2(__float2half_rn(r0.x), __float2half_rn(r1.x));
    d[1] = __halves2half2(__float2half_rn(r0.y), __float2half_rn(r1.y));
    d[2] = __halves2half2(__float2half_rn(r0.z), __float2half_rn(r1.z));
    d[3] = __halves2half2(__float2half_rn(r0.w), __float2half_rn(r1.w));
}

#define WCH0 393216
#define WCH1 (WCH0 + 131072)
#define WCH2 (WCH1 + 524288)
#define WCH3 (WCH2 + 524288)

__global__ void __launch_bounds__(256) wprep_all_kernel(
    const float* __restrict__ s0, __half* __restrict__ d0,
    const float* __restrict__ s1, __half* __restrict__ d1,
    const float* __restrict__ s2, __half* __restrict__ d2,
    const float* __restrict__ s3, __half* __restrict__ d3)
{
    #pragma unroll
    for (int u = 0; u < 2; u++) {
        const int g = (blockIdx.x * 2 + u) * 256 + threadIdx.x;
        if (g >= WCH3) return;
        if      (g < WCH0) wprep_chunk(s0, d0, 3 * C_, g);
        else if (g < WCH1) wprep_chunk(s1, d1, C_,     g - WCH0);
        else if (g < WCH2) wprep_chunk(s2, d2, FF_,    g - WCH1);
        else               wprep_chunk(s3, d3, C_,     g - WCH2);
    }
}

// ---------------------------------------------------------------------------
// LayerNorm: warp-per-row, pure shuffle reduction. Outputs fp16.
// ---------------------------------------------------------------------------
__global__ void __launch_bounds__(256) ln_kernel(
    const float* __restrict__ x, const float* __restrict__ w,
    const float* __restrict__ b, __half* __restrict__ out)
{
    const int lane = threadIdx.x & 31;
    const int row  = blockIdx.x * 8 + (threadIdx.x >> 5);
    const float4* xp = (const float4*)(x + (size_t)row * C_);

    float4 v[8];
    float s = 0.f, s2 = 0.f;
    #pragma unroll
    for (int i = 0; i < 8; i++) {
        v[i] = xp[lane + 32 * i];
        s  += v[i].x + v[i].y + v[i].z + v[i].w;
        s2 += v[i].x*v[i].x + v[i].y*v[i].y + v[i].z*v[i].z + v[i].w*v[i].w;
    }
    #pragma unroll
    for (int o = 16; o > 0; o >>= 1) {
        s  += __shfl_xor_sync(0xffffffffu, s,  o);
        s2 += __shfl_xor_sync(0xffffffffu, s2, o);
    }
    const float mean = s * (1.0f / C_);
    const float var  = s2 * (1.0f / C_) - mean * mean;
    const float rstd = rsqrtf(var + 1e-5f);

    uint2* op = (uint2*)(out + (size_t)row * C_);
    #pragma unroll
    for (int i = 0; i < 8; i++) {
        const float4 wv = ((const float4*)w)[lane + 32 * i];
        const float4 bv = ((const float4*)b)[lane + 32 * i];
        uint2 u;
        u.x = packh2((v[i].x - mean) * rstd * wv.x + bv.x,
                     (v[i].y - mean) * rstd * wv.y + bv.y);
        u.y = packh2((v[i].z - mean) * rstd * wv.z + bv.z,
                     (v[i].w - mean) * rstd * wv.w + bv.w);
        op[lane + 32 * i] = u;
    }
}

// ---------------------------------------------------------------------------
// FP16 tensor-core GEMM (proven R9/R11 kernel, f32 accumulators, BN=128).
// ---------------------------------------------------------------------------
#define BM 128
#define BN 128
#define BK 32
#define STAGES 3
#define A_STR 40
#define B_STR 272
#define A_TILE_H (BM * A_STR)
#define B_TILE_H (16 * B_STR)
#define SMEM_BYTES (STAGES * (A_TILE_H + B_TILE_H) * 2)   // 56832

template<int ACT, int RES, int OUT>
__global__ void __launch_bounds__(256) gemm_h_kernel(
    const __half* __restrict__ A, const __half* __restrict__ Wp,
    const float* __restrict__ bias, const float* __restrict__ res,
    void* __restrict__ outv, int M, int N, int K)
{
    extern __shared__ __half hsm[];
    __half* As = hsm;
    __half* Bs = hsm + STAGES * A_TILE_H;

    const int tid  = threadIdx.x;
    const int lane = tid & 31;
    const int wid  = tid >> 5;
    const int wm   = wid >> 2;
    const int wn   = wid & 3;
    const int bm   = blockIdx.y;
    const int bn   = blockIdx.x;
    const int fr   = lane >> 2;
    const int fc   = lane & 3;

    float acc[4][4][4];
    #pragma unroll
    for (int i = 0; i < 4; i++)
        #pragma unroll
        for (int j = 0; j < 4; j++)
            #pragma unroll
            for (int r = 0; r < 4; r++) acc[i][j][r] = 0.f;

    const int ntiles = K / BK;

    auto load_tile = [&](int t, int stg) {
        const int k0 = t * BK;
        __half* Ab = As + stg * A_TILE_H;
        __half* Bb = Bs + stg * B_TILE_H;
        #pragma unroll
        for (int i = 0; i < 2; i++) {
            const int idx = i * 256 + tid;
            const int row = idx >> 2, c4 = idx & 3;
            cp_async16(Ab + row * A_STR + c4 * 8,
                       A + (size_t)(bm * BM + row) * K + k0 + c4 * 8);
        }
        const int kp0 = k0 >> 1;
        #pragma unroll
        for (int i = 0; i < 2; i++) {
            const int idx = i * 256 + tid;
            const int kp = idx >> 5, ch = idx & 31;
            cp_async16(Bb + kp * B_STR + ch * 8,
                       Wp + (size_t)(kp0 + kp) * (2 * N) + (size_t)bn * (2 * BN) + ch * 8);
        }
        cp_commit();
    };

    load_tile(0, 0);
    load_tile(1, 1);

    for (int t = 0; t < ntiles; t++) {
        if (t + 2 < ntiles) load_tile(t + 2, (t + 2) % STAGES);
        else                cp_commit();
        cp_wait<2>();
        __syncthreads();

        const __half* Ab = As + (t % STAGES) * A_TILE_H;
        const __half* Bb = Bs + (t % STAGES) * B_TILE_H;

        #pragma unroll
        for (int ks = 0; ks < 2; ks++) {
            const int kc = ks * 16;
            uint32_t af[4][4], bf[4][2];
            #pragma unroll
            for (int mi = 0; mi < 4; mi++) {
                const int base = (wm * 64 + mi * 16 + fr) * A_STR + kc + 2 * fc;
                af[mi][0] = *(const uint32_t*)&Ab[base];
                af[mi][1] = *(const uint32_t*)&Ab[base + 8 * A_STR];
                af[mi][2] = *(const uint32_t*)&Ab[base + 8];
                af[mi][3] = *(const uint32_t*)&Ab[base + 8 * A_STR + 8];
            }
            const int kp = ks * 8 + fc;
            #pragma unroll
            for (int ni = 0; ni < 4; ni++) {
                const int n2 = 2 * (wn * 32 + ni * 8 + fr);
                bf[ni][0] = *(const uint32_t*)&Bb[kp * B_STR + n2];
                bf[ni][1] = *(const uint32_t*)&Bb[(kp + 4) * B_STR + n2];
            }
            #pragma unroll
            for (int mi = 0; mi < 4; mi++)
                #pragma unroll
                for (int ni = 0; ni < 4; ni++)
                    mma_f16(acc[mi][ni][0], acc[mi][ni][1],
                            acc[mi][ni][2], acc[mi][ni][3],
                            af[mi][0], af[mi][1], af[mi][2], af[mi][3],
                            bf[ni][0], bf[ni][1]);
        }
        __syncthreads();
    }

    #pragma unroll
    for (int mi = 0; mi < 4; mi++) {
        const int row0 = bm * BM + wm * 64 + mi * 16 + fr;
        #pragma unroll
        for (int ni = 0; ni < 4; ni++) {
            const int col = bn * BN + wn * 32 + ni * 8 + fc * 2;
            const float b0 = bias[col], b1 = bias[col + 1];

            float v0 = acc[mi][ni][0] + b0;
            float v1 = acc[mi][ni][1] + b1;
            float v2 = acc[mi][ni][2] + b0;
            float v3 = acc[mi][ni][3] + b1;
            if (ACT == 1) {
                v0 = gelu_exact(v0); v1 = gelu_exact(v1);
                v2 = gelu_exact(v2); v3 = gelu_exact(v3);
            }
            if (RES) {
                const float2 r0 = *(const float2*)(res + (size_t)row0 * N + col);
                const float2 r1 = *(const float2*)(res + (size_t)(row0 + 8) * N + col);
                v0 += r0.x; v1 += r0.y; v2 += r1.x; v3 += r1.y;
            }
            if (OUT == 2) {
                __half* out = (__half*)outv;
                *(uint32_t*)(out + (size_t)row0 * N + col)       = packh2(v0, v1);
                *(uint32_t*)(out + (size_t)(row0 + 8) * N + col) = packh2(v2, v3);
            } else {
                if (OUT == 1) {
                    v0 = tf32_round(v0); v1 = tf32_round(v1);
                    v2 = tf32_round(v2); v3 = tf32_round(v3);
                }
                float* out = (float*)outv;
                *(float2*)(out + (size_t)row0 * N + col)       = make_float2(v0, v1);
                *(float2*)(out + (size_t)(row0 + 8) * N + col) = make_float2(v2, v3);
            }
        }
    }
}

// ---------------------------------------------------------------------------
// FP16 causal flash attention, register-resident Q and P.
// Key fact: m16n8k16 C-fragment layout == A-fragment layout per lane, so the
// softmax probabilities are packed straight into PV A-operands (no SMEM P).
// SMEM: double-buffered K,V only (36864 B) -> higher occupancy.
// ---------------------------------------------------------------------------
#define HS 72
#define KVH (64 * HS)
#define ATTN_SMEM_BYTES (4 * KVH * 2)   // 2K + 2V = 36864 B

__global__ void __launch_bounds__(128, 5) attn_h_kernel(
    const __half* __restrict__ qkv, __half* __restrict__ y)
{
    extern __shared__ __half asm_[];
    __half* Ks = asm_;             // 2 buffers
    __half* Vs = Ks + 2 * KVH;     // 2 buffers

    const int qt   = (int)(gridDim.x - 1 - blockIdx.x);   // heavy tiles first
    const int h    = blockIdx.y;
    const int b    = blockIdx.z;
    const int tid  = threadIdx.x;
    const int lane = tid & 31;
    const int w    = tid >> 5;
    const int fr   = lane >> 2;
    const int fc   = lane & 3;

    const size_t base = (size_t)(b * T_) * (3 * C_) + h * D_;
    const int rlo = w * 16 + fr;

    // ---- Q into registers (A-fragment layout), plus first K/V tile ----
    uint32_t qf[4][4];
    {
        const __half* q0 = qkv + base + (size_t)(qt * 64 + rlo) * (3 * C_);
        const __half* q1 = q0 + 8 * (3 * C_);
        #pragma unroll
        for (int s = 0; s < 4; s++) {
            const int kc = s * 16 + 2 * fc;
            qf[s][0] = *(const uint32_t*)&q0[kc];
            qf[s][1] = *(const uint32_t*)&q1[kc];
            qf[s][2] = *(const uint32_t*)&q0[kc + 8];
            qf[s][3] = *(const uint32_t*)&q1[kc + 8];
        }
        #pragma unroll
        for (int i = 0; i < 4; i++) {
            const int idx = i * 128 + tid;
            const int r = idx >> 3, ch = idx & 7;
            const __half* src = qkv + base + (size_t)r * (3 * C_) + ch * 8;
            cp_async16(Ks + r * HS + ch * 8, src + C_);
            cp_async16(Vs + r * HS + ch * 8, src + 2 * C_);
        }
        cp_commit();
    }

    auto load_kv = [&](int kt, int bufi) {
        __half* Kb = Ks + bufi * KVH;
        __half* Vb = Vs + bufi * KVH;
        #pragma unroll
        for (int i = 0; i < 4; i++) {
            const int idx = i * 128 + tid;
            const int r = idx >> 3, ch = idx & 7;
            const __half* src = qkv + base + (size_t)(kt * 64 + r) * (3 * C_) + ch * 8;
            cp_async16(Kb + r * HS + ch * 8, src + C_);
            cp_async16(Vb + r * HS + ch * 8, src + 2 * C_);
        }
        cp_commit();
    };

    float accO[8][4];
    #pragma unroll
    for (int ni = 0; ni < 8; ni++)
        #pragma unroll
        for (int r = 0; r < 4; r++) accO[ni][r] = 0.f;
    float m0 = -INFINITY, m1 = -INFINITY, l0 = 0.f, l1 = 0.f;

    int buf = 0;
    for (int kt = 0; kt <= qt; kt++) {
        if (kt < qt) { load_kv(kt + 1, buf ^ 1); cp_wait<1>(); }
        else         { cp_wait<0>(); }
        __syncthreads();

        const __half* Kb = Ks + buf * KVH;
        const __half* Vb = Vs + buf * KVH;

        // ---- S = Q K^T ----
        float accS[8][4];
        #pragma unroll
        for (int ni = 0; ni < 8; ni++)
            #pragma unroll
            for (int r = 0; r < 4; r++) accS[ni][r] = 0.f;

        #pragma unroll
        for (int s = 0; s < 4; s++) {
            const int kc = s * 16;
            #pragma unroll
            for (int ni = 0; ni < 8; ni++) {
                const uint32_t b0 = *(const uint32_t*)&Kb[(ni*8 + fr) * HS + kc + 2*fc];
                const uint32_t b1 = *(const uint32_t*)&Kb[(ni*8 + fr) * HS + kc + 8 + 2*fc];
                mma_f16(accS[ni][0], accS[ni][1], accS[ni][2], accS[ni][3],
                        qf[s][0], qf[s][1], qf[s][2], qf[s][3], b0, b1);
            }
        }

        // ---- scale + mask + online softmax; pack P into A-fragments ----
        const bool diag = (kt == qt);
        float mx0 = -INFINITY, mx1 = -INFINITY;
        #pragma unroll
        for (int ni = 0; ni < 8; ni++) {
            float s0 = accS[ni][0] * 0.125f;
            float s1 = accS[ni][1] * 0.125f;
            float s2 = accS[ni][2] * 0.125f;
            float s3 = accS[ni][3] * 0.125f;
            if (diag) {
                const int j = ni * 8 + 2 * fc;
                if (j     > rlo    ) s0 = -INFINITY;
                if (j + 1 > rlo    ) s1 = -INFINITY;
                if (j     > rlo + 8) s2 = -INFINITY;
                if (j + 1 > rlo + 8) s3 = -INFINITY;
            }
            accS[ni][0] = s0; accS[ni][1] = s1;
            accS[ni][2] = s2; accS[ni][3] = s3;
            mx0 = fmaxf(mx0, fmaxf(s0, s1));
            mx1 = fmaxf(mx1, fmaxf(s2, s3));
        }
        mx0 = fmaxf(mx0, __shfl_xor_sync(0xffffffffu, mx0, 1));
        mx0 = fmaxf(mx0, __shfl_xor_sync(0xffffffffu, mx0, 2));
        mx1 = fmaxf(mx1, __shfl_xor_sync(0xffffffffu, mx1, 1));
        mx1 = fmaxf(mx1, __shfl_xor_sync(0xffffffffu, mx1, 2));

        const float mn0 = fmaxf(m0, mx0);
        const float mn1 = fmaxf(m1, mx1);
        const float c0 = __expf(m0 - mn0);
        const float c1 = __expf(m1 - mn1);

        uint32_t paf[8][2];
        float ls0 = 0.f, ls1 = 0.f;
        #pragma unroll
        for (int ni = 0; ni < 8; ni++) {
            const float p0 = __expf(accS[ni][0] - mn0);
            const float p1 = __expf(accS[ni][1] - mn0);
            const float p2 = __expf(accS[ni][2] - mn1);
            const float p3 = __expf(accS[ni][3] - mn1);
            ls0 += p0 + p1;  ls1 += p2 + p3;
            accO[ni][0] *= c0; accO[ni][1] *= c0;
            accO[ni][2] *= c1; accO[ni][3] *= c1;
            paf[ni][0] = packh2(p0, p1);     // rows fr   : A-frag a0/a2 source
            paf[ni][1] = packh2(p2, p3);     // rows fr+8 : A-frag a1/a3 source
        }
        ls0 += __shfl_xor_sync(0xffffffffu, ls0, 1);
        ls0 += __shfl_xor_sync(0xffffffffu, ls0, 2);
        ls1 += __shfl_xor_sync(0xffffffffu, ls1, 1);
        ls1 += __shfl_xor_sync(0xffffffffu, ls1, 2);
        l0 = l0 * c0 + ls0;
        l1 = l1 * c1 + ls1;
        m0 = mn0; m1 = mn1;

        // ---- O += P V  (P from regs; V via ldmatrix.trans) ----
        const uint32_t vbase = (uint32_t)__cvta_generic_to_shared(Vb);
        const int mat = lane >> 3, rin = lane & 7;
        #pragma unroll
        for (int s = 0; s < 4; s++) {
            const int kc = s * 16;
            const uint32_t a0 = paf[2*s    ][0];
            const uint32_t a1 = paf[2*s    ][1];
            const uint32_t a2 = paf[2*s + 1][0];
            const uint32_t a3 = paf[2*s + 1][1];
            #pragma unroll
            for (int np = 0; np < 4; np++) {
                const int ni  = 2 * np;
                const int row = kc + ((mat & 1) ? 8 : 0) + rin;
                const int col = ni * 8 + ((mat & 2) ? 8 : 0);
                uint32_t b0, b1, b2, b3;
                ldmx4t(b0, b1, b2, b3, vbase + (uint32_t)(row * HS + col) * 2);
                mma_f16(accO[ni][0], accO[ni][1], accO[ni][2], accO[ni][3],
                        a0, a1, a2, a3, b0, b1);
                mma_f16(accO[ni+1][0], accO[ni+1][1], accO[ni+1][2], accO[ni+1][3],
                        a0, a1, a2, a3, b2, b3);
            }
        }

        __syncthreads();
        buf ^= 1;
    }

    const float inv0 = 1.f / l0;
    const float inv1 = 1.f / l1;
    const size_t grow = (size_t)(b * T_ + qt * 64 + rlo);
    #pragma unroll
    for (int ni = 0; ni < 8; ni++) {
        const int col = h * D_ + ni * 8 + 2 * fc;
        *(uint32_t*)(y + grow * C_ + col) =
            packh2(accO[ni][0] * inv0, accO[ni][1] * inv0);
        *(uint32_t*)(y + (grow + 8) * C_ + col) =
            packh2(accO[ni][2] * inv1, accO[ni][3] * inv1);
    }
}

// ---------------------------------------------------------------------------
// Launch
// ---------------------------------------------------------------------------
extern "C" void kernel_launch(void* const* d_in, const int* in_sizes, int n_in,
                              void* d_out, int out_size)
{
    (void)in_sizes; (void)n_in; (void)out_size;
    const float* x     = (const float*)d_in[0];
    const float* ln1_w = (const float*)d_in[1];
    const float* ln1_b = (const float*)d_in[2];
    const float* w_qkv = (const float*)d_in[3];
    const float* b_qkv = (const float*)d_in[4];
    const float* w_o   = (const float*)d_in[5];
    const float* b_o   = (const float*)d_in[6];
    const float* ln2_w = (const float*)d_in[7];
    const float* ln2_b = (const float*)d_in[8];
    const float* w_fc  = (const float*)d_in[9];
    const float* b_fc  = (const float*)d_in[10];
    const float* w_out = (const float*)d_in[11];
    const float* b_out = (const float*)d_in[12];
    float* out = (float*)d_out;

    __half *xn, *qkv, *y, *hbuf, *wq, *wo, *wf, *wu;
    float *x1;
    cudaGetSymbolAddress((void**)&xn,   g_xn);
    cudaGetSymbolAddress((void**)&qkv,  g_qkv);
    cudaGetSymbolAddress((void**)&y,    g_y);
    cudaGetSymbolAddress((void**)&x1,   g_x1);
    cudaGetSymbolAddress((void**)&hbuf, g_h);
    cudaGetSymbolAddress((void**)&wq,   g_wqkv);
    cudaGetSymbolAddress((void**)&wo,   g_wo);
    cudaGetSymbolAddress((void**)&wf,   g_wfc);
    cudaGetSymbolAddress((void**)&wu,   g_wout);

    cudaFuncSetAttribute(gemm_h_kernel<0,0,2>,
        cudaFuncAttributeMaxDynamicSharedMemorySize, SMEM_BYTES);
    cudaFuncSetAttribute(gemm_h_kernel<0,1,0>,
        cudaFuncAttributeMaxDynamicSharedMemorySize, SMEM_BYTES);
    cudaFuncSetAttribute(gemm_h_kernel<1,0,2>,
        cudaFuncAttributeMaxDynamicSharedMemorySize, SMEM_BYTES);
    cudaFuncSetAttribute(attn_h_kernel,
        cudaFuncAttributeMaxDynamicSharedMemorySize, ATTN_SMEM_BYTES);

    // 0) fused weight prep (all 4 weights, one launch)
    wprep_all_kernel<<<WCH3 / 512, 256>>>(
        w_qkv, wq, w_o, wo, w_fc, wf, w_out, wu);

    // 1) LN1 -> fp16
    ln_kernel<<<M_ / 8, 256>>>(x, ln1_w, ln1_b, xn);
    // 2) qkv = xn @ w_qkv + b_qkv  -> fp16
    gemm_h_kernel<0,0,2><<<dim3(3 * C_ / BN, M_ / BM), 256, SMEM_BYTES>>>(
        xn, wq, b_qkv, nullptr, qkv, M_, 3 * C_, C_);
    // 3) causal attention (fp16) -> y (fp16)
    attn_h_kernel<<<dim3(T_ / 64, H_, B_), 128, ATTN_SMEM_BYTES>>>(qkv, y);
    // 4) x1 = x + y @ w_o + b_o (fp32)
    gemm_h_kernel<0,1,0><<<dim3(C_ / BN, M_ / BM), 256, SMEM_BYTES>>>(
        y, wo, b_o, x, x1, M_, C_, C_);
    // 5) LN2 -> fp16
    ln_kernel<<<M_ / 8, 256>>>(x1, ln2_w, ln2_b, xn);
    // 6) h = gelu(xn @ w_fc + b_fc) -> fp16
    gemm_h_kernel<1,0,2><<<dim3(FF_ / BN, M_ / BM), 256, SMEM_BYTES>>>(
        xn, wf, b_fc, nullptr, hbuf, M_, FF_, C_);
    // 7) out = x1 + h @ w_out + b_out (fp32)
    gemm_h_kernel<0,1,0><<<dim3(C_ / BN, M_ / BM), 256, SMEM_BYTES>>>(
        hbuf, wu, b_out, x1, out, M_, C_, FF_);
}

// round 14
// speedup vs baseline: 1.0224x; 1.0070x over previous
#include <cuda_runtime.h>
#include <cuda_fp16.h>
#include <math.h>
#include <stdint.h>

// Problem constants
#define B_  4
#define T_  2048
#define H_  16
#define D_  64
#define C_  1024
#define FF_ 4096
#define M_  (B_ * T_)   // 8192 rows

// ---------------------------------------------------------------------------
// Scratch (device globals — no runtime allocation allowed)
// ---------------------------------------------------------------------------
__device__ __half g_xn  [M_ * C_];
__device__ __half g_qkv [M_ * 3 * C_];
__device__ __half g_y   [M_ * C_];
__device__ float  g_x1  [M_ * C_];
__device__ __half g_h   [M_ * FF_];
__device__ __half g_wqkv[C_ * 3 * C_];
__device__ __half g_wo  [C_ * C_];
__device__ __half g_wfc [C_ * FF_];
__device__ __half g_wout[FF_ * C_];

// ---------------------------------------------------------------------------
// Helpers
// ---------------------------------------------------------------------------
__device__ __forceinline__ uint32_t f2tf32(float f) {
    uint32_t r;
    asm("cvt.rna.tf32.f32 %0, %1;" : "=r"(r) : "f"(f));
    return r;
}
__device__ __forceinline__ float tf32_round(float f) {
    return __uint_as_float(f2tf32(f));
}

__device__ __forceinline__ void mma_f16(
    float& d0, float& d1, float& d2, float& d3,
    uint32_t a0, uint32_t a1, uint32_t a2, uint32_t a3,
    uint32_t b0, uint32_t b1)
{
    asm volatile(
        "mma.sync.aligned.m16n8k16.row.col.f32.f16.f16.f32 "
        "{%0,%1,%2,%3}, {%4,%5,%6,%7}, {%8,%9}, {%0,%1,%2,%3};\n"
        : "+f"(d0), "+f"(d1), "+f"(d2), "+f"(d3)
        : "r"(a0), "r"(a1), "r"(a2), "r"(a3), "r"(b0), "r"(b1));
}

__device__ __forceinline__ void ldmx4(
    uint32_t& d0, uint32_t& d1, uint32_t& d2, uint32_t& d3, uint32_t addr)
{
    asm volatile(
        "ldmatrix.sync.aligned.m8n8.x4.shared.b16 {%0,%1,%2,%3}, [%4];"
        : "=r"(d0), "=r"(d1), "=r"(d2), "=r"(d3) : "r"(addr));
}
__device__ __forceinline__ void ldmx4t(
    uint32_t& d0, uint32_t& d1, uint32_t& d2, uint32_t& d3, uint32_t addr)
{
    asm volatile(
        "ldmatrix.sync.aligned.m8n8.x4.trans.shared.b16 {%0,%1,%2,%3}, [%4];"
        : "=r"(d0), "=r"(d1), "=r"(d2), "=r"(d3) : "r"(addr));
}

__device__ __forceinline__ void cp_async16(void* dst_smem, const void* src) {
    uint32_t d = (uint32_t)__cvta_generic_to_shared(dst_smem);
    asm volatile("cp.async.cg.shared.global [%0], [%1], 16;\n" :: "r"(d), "l"(src));
}
__device__ __forceinline__ void cp_commit() {
    asm volatile("cp.async.commit_group;\n");
}
template<int N>
__device__ __forceinline__ void cp_wait() {
    asm volatile("cp.async.wait_group %0;\n" :: "n"(N));
}

__device__ __forceinline__ float gelu_exact(float x) {
    return 0.5f * x * (1.0f + erff(x * 0.70710678118654752f));
}
__device__ __forceinline__ uint32_t packh2(float a, float b) {
    __half2 h = __halves2half2(__float2half_rn(a), __float2half_rn(b));
    return *(uint32_t*)&h;
}

// ---------------------------------------------------------------------------
// Fused weight prep: all 4 weights, fp32 [K][N] -> fp16 interleaved
// ---------------------------------------------------------------------------
__device__ __forceinline__ void wprep_chunk(
    const float* __restrict__ src, __half* __restrict__ dst, int N, int idx)
{
    const int nq = N >> 2;
    const int kp = idx / nq;
    const int n4 = idx - kp * nq;
    const float4 r0 = *(const float4*)(src + (size_t)(2 * kp)     * N + 4 * n4);
    const float4 r1 = *(const float4*)(src + (size_t)(2 * kp + 1) * N + 4 * n4);
    __half2* d = (__half2*)(dst + (size_t)kp * (2 * N) + 8 * n4);
    d[0] = __halves2half2(__float2half_rn(r0.x), __float2half_rn(r1.x));
    d[1] = __halves2half2(__float2half_rn(r0.y), __float2half_rn(r1.y));
    d[2] = __halves2half2(__float2half_rn(r0.z), __float2half_rn(r1.z));
    d[3] = __halves2half2(__float2half_rn(r0.w), __float2half_rn(r1.w));
}

#define WCH0 393216
#define WCH1 (WCH0 + 131072)
#define WCH2 (WCH1 + 524288)
#define WCH3 (WCH2 + 524288)

__global__ void __launch_bounds__(256) wprep_all_kernel(
    const float* __restrict__ s0, __half* __restrict__ d0,
    const float* __restrict__ s1, __half* __restrict__ d1,
    const float* __restrict__ s2, __half* __restrict__ d2,
    const float* __restrict__ s3, __half* __restrict__ d3)
{
    #pragma unroll
    for (int u = 0; u < 2; u++) {
        const int g = (blockIdx.x * 2 + u) * 256 + threadIdx.x;
        if (g >= WCH3) return;
        if      (g < WCH0) wprep_chunk(s0, d0, 3 * C_, g);
        else if (g < WCH1) wprep_chunk(s1, d1, C_,     g - WCH0);
        else if (g < WCH2) wprep_chunk(s2, d2, FF_,    g - WCH1);
        else               wprep_chunk(s3, d3, C_,     g - WCH2);
    }
}

// ---------------------------------------------------------------------------
// LayerNorm: warp-per-row, pure shuffle reduction. Outputs fp16.
// ---------------------------------------------------------------------------
__global__ void __launch_bounds__(256) ln_kernel(
    const float* __restrict__ x, const float* __restrict__ w,
    const float* __restrict__ b, __half* __restrict__ out)
{
    const int lane = threadIdx.x & 31;
    const int row  = blockIdx.x * 8 + (threadIdx.x >> 5);
    const float4* xp = (const float4*)(x + (size_t)row * C_);

    float4 v[8];
    float s = 0.f, s2 = 0.f;
    #pragma unroll
    for (int i = 0; i < 8; i++) {
        v[i] = xp[lane + 32 * i];
        s  += v[i].x + v[i].y + v[i].z + v[i].w;
        s2 += v[i].x*v[i].x + v[i].y*v[i].y + v[i].z*v[i].z + v[i].w*v[i].w;
    }
    #pragma unroll
    for (int o = 16; o > 0; o >>= 1) {
        s  += __shfl_xor_sync(0xffffffffu, s,  o);
        s2 += __shfl_xor_sync(0xffffffffu, s2, o);
    }
    const float mean = s * (1.0f / C_);
    const float var  = s2 * (1.0f / C_) - mean * mean;
    const float rstd = rsqrtf(var + 1e-5f);

    uint2* op = (uint2*)(out + (size_t)row * C_);
    #pragma unroll
    for (int i = 0; i < 8; i++) {
        const float4 wv = ((const float4*)w)[lane + 32 * i];
        const float4 bv = ((const float4*)b)[lane + 32 * i];
        uint2 u;
        u.x = packh2((v[i].x - mean) * rstd * wv.x + bv.x,
                     (v[i].y - mean) * rstd * wv.y + bv.y);
        u.y = packh2((v[i].z - mean) * rstd * wv.z + bv.z,
                     (v[i].w - mean) * rstd * wv.w + bv.w);
        op[lane + 32 * i] = u;
    }
}

// ---------------------------------------------------------------------------
// FP16 tensor-core GEMM (proven kernel, f32 accumulators, BN=128).
// ---------------------------------------------------------------------------
#define BM 128
#define BN 128
#define BK 32
#define STAGES 3
#define A_STR 40
#define B_STR 272
#define A_TILE_H (BM * A_STR)
#define B_TILE_H (16 * B_STR)
#define SMEM_BYTES (STAGES * (A_TILE_H + B_TILE_H) * 2)   // 56832

template<int ACT, int RES, int OUT>
__global__ void __launch_bounds__(256) gemm_h_kernel(
    const __half* __restrict__ A, const __half* __restrict__ Wp,
    const float* __restrict__ bias, const float* __restrict__ res,
    void* __restrict__ outv, int M, int N, int K)
{
    extern __shared__ __half hsm[];
    __half* As = hsm;
    __half* Bs = hsm + STAGES * A_TILE_H;

    const int tid  = threadIdx.x;
    const int lane = tid & 31;
    const int wid  = tid >> 5;
    const int wm   = wid >> 2;
    const int wn   = wid & 3;
    const int bm   = blockIdx.y;
    const int bn   = blockIdx.x;
    const int fr   = lane >> 2;
    const int fc   = lane & 3;

    float acc[4][4][4];
    #pragma unroll
    for (int i = 0; i < 4; i++)
        #pragma unroll
        for (int j = 0; j < 4; j++)
            #pragma unroll
            for (int r = 0; r < 4; r++) acc[i][j][r] = 0.f;

    const int ntiles = K / BK;

    auto load_tile = [&](int t, int stg) {
        const int k0 = t * BK;
        __half* Ab = As + stg * A_TILE_H;
        __half* Bb = Bs + stg * B_TILE_H;
        #pragma unroll
        for (int i = 0; i < 2; i++) {
            const int idx = i * 256 + tid;
            const int row = idx >> 2, c4 = idx & 3;
            cp_async16(Ab + row * A_STR + c4 * 8,
                       A + (size_t)(bm * BM + row) * K + k0 + c4 * 8);
        }
        const int kp0 = k0 >> 1;
        #pragma unroll
        for (int i = 0; i < 2; i++) {
            const int idx = i * 256 + tid;
            const int kp = idx >> 5, ch = idx & 31;
            cp_async16(Bb + kp * B_STR + ch * 8,
                       Wp + (size_t)(kp0 + kp) * (2 * N) + (size_t)bn * (2 * BN) + ch * 8);
        }
        cp_commit();
    };

    load_tile(0, 0);
    load_tile(1, 1);

    for (int t = 0; t < ntiles; t++) {
        if (t + 2 < ntiles) load_tile(t + 2, (t + 2) % STAGES);
        else                cp_commit();
        cp_wait<2>();
        __syncthreads();

        const __half* Ab = As + (t % STAGES) * A_TILE_H;
        const __half* Bb = Bs + (t % STAGES) * B_TILE_H;

        #pragma unroll
        for (int ks = 0; ks < 2; ks++) {
            const int kc = ks * 16;
            uint32_t af[4][4], bf[4][2];
            #pragma unroll
            for (int mi = 0; mi < 4; mi++) {
                const int base = (wm * 64 + mi * 16 + fr) * A_STR + kc + 2 * fc;
                af[mi][0] = *(const uint32_t*)&Ab[base];
                af[mi][1] = *(const uint32_t*)&Ab[base + 8 * A_STR];
                af[mi][2] = *(const uint32_t*)&Ab[base + 8];
                af[mi][3] = *(const uint32_t*)&Ab[base + 8 * A_STR + 8];
            }
            const int kp = ks * 8 + fc;
            #pragma unroll
            for (int ni = 0; ni < 4; ni++) {
                const int n2 = 2 * (wn * 32 + ni * 8 + fr);
                bf[ni][0] = *(const uint32_t*)&Bb[kp * B_STR + n2];
                bf[ni][1] = *(const uint32_t*)&Bb[(kp + 4) * B_STR + n2];
            }
            #pragma unroll
            for (int mi = 0; mi < 4; mi++)
                #pragma unroll
                for (int ni = 0; ni < 4; ni++)
                    mma_f16(acc[mi][ni][0], acc[mi][ni][1],
                            acc[mi][ni][2], acc[mi][ni][3],
                            af[mi][0], af[mi][1], af[mi][2], af[mi][3],
                            bf[ni][0], bf[ni][1]);
        }
        __syncthreads();
    }

    #pragma unroll
    for (int mi = 0; mi < 4; mi++) {
        const int row0 = bm * BM + wm * 64 + mi * 16 + fr;
        #pragma unroll
        for (int ni = 0; ni < 4; ni++) {
            const int col = bn * BN + wn * 32 + ni * 8 + fc * 2;
            const float b0 = bias[col], b1 = bias[col + 1];

            float v0 = acc[mi][ni][0] + b0;
            float v1 = acc[mi][ni][1] + b1;
            float v2 = acc[mi][ni][2] + b0;
            float v3 = acc[mi][ni][3] + b1;
            if (ACT == 1) {
                v0 = gelu_exact(v0); v1 = gelu_exact(v1);
                v2 = gelu_exact(v2); v3 = gelu_exact(v3);
            }
            if (RES) {
                const float2 r0 = *(const float2*)(res + (size_t)row0 * N + col);
                const float2 r1 = *(const float2*)(res + (size_t)(row0 + 8) * N + col);
                v0 += r0.x; v1 += r0.y; v2 += r1.x; v3 += r1.y;
            }
            if (OUT == 2) {
                __half* out = (__half*)outv;
                *(uint32_t*)(out + (size_t)row0 * N + col)       = packh2(v0, v1);
                *(uint32_t*)(out + (size_t)(row0 + 8) * N + col) = packh2(v2, v3);
            } else {
                if (OUT == 1) {
                    v0 = tf32_round(v0); v1 = tf32_round(v1);
                    v2 = tf32_round(v2); v3 = tf32_round(v3);
                }
                float* out = (float*)outv;
                *(float2*)(out + (size_t)row0 * N + col)       = make_float2(v0, v1);
                *(float2*)(out + (size_t)(row0 + 8) * N + col) = make_float2(v2, v3);
            }
        }
    }
}

// ---------------------------------------------------------------------------
// FP16 causal flash attention, register-resident Q and P, ldmatrix K/V,
// log2-domain softmax (single fp32 scale; exp2f only).
// ---------------------------------------------------------------------------
#define HS 72
#define KVH (64 * HS)
#define ATTN_SMEM_BYTES (4 * KVH * 2)   // 2K + 2V = 36864 B
#define SCALE_L2E 0.18033688011112042f  // 0.125 * log2(e)

__global__ void __launch_bounds__(128, 5) attn_h_kernel(
    const __half* __restrict__ qkv, __half* __restrict__ y)
{
    extern __shared__ __half asm_[];
    __half* Ks = asm_;             // 2 buffers
    __half* Vs = Ks + 2 * KVH;     // 2 buffers

    const int qt   = (int)(gridDim.x - 1 - blockIdx.x);   // heavy tiles first
    const int h    = blockIdx.y;
    const int b    = blockIdx.z;
    const int tid  = threadIdx.x;
    const int lane = tid & 31;
    const int w    = tid >> 5;
    const int fr   = lane >> 2;
    const int fc   = lane & 3;
    const int mat  = lane >> 3;    // ldmatrix group 0..3
    const int rin  = lane & 7;

    const size_t base = (size_t)(b * T_) * (3 * C_) + h * D_;
    const int rlo = w * 16 + fr;

    // ---- Q into registers (A-fragment layout), plus first K/V tile ----
    uint32_t qf[4][4];
    {
        const __half* q0 = qkv + base + (size_t)(qt * 64 + rlo) * (3 * C_);
        const __half* q1 = q0 + 8 * (3 * C_);
        #pragma unroll
        for (int s = 0; s < 4; s++) {
            const int kc = s * 16 + 2 * fc;
            qf[s][0] = *(const uint32_t*)&q0[kc];
            qf[s][1] = *(const uint32_t*)&q1[kc];
            qf[s][2] = *(const uint32_t*)&q0[kc + 8];
            qf[s][3] = *(const uint32_t*)&q1[kc + 8];
        }
        #pragma unroll
        for (int i = 0; i < 4; i++) {
            const int idx = i * 128 + tid;
            const int r = idx >> 3, ch = idx & 7;
            const __half* src = qkv + base + (size_t)r * (3 * C_) + ch * 8;
            cp_async16(Ks + r * HS + ch * 8, src + C_);
            cp_async16(Vs + r * HS + ch * 8, src + 2 * C_);
        }
        cp_commit();
    }

    auto load_kv = [&](int kt, int bufi) {
        __half* Kb = Ks + bufi * KVH;
        __half* Vb = Vs + bufi * KVH;
        #pragma unroll
        for (int i = 0; i < 4; i++) {
            const int idx = i * 128 + tid;
            const int r = idx >> 3, ch = idx & 7;
            const __half* src = qkv + base + (size_t)(kt * 64 + r) * (3 * C_) + ch * 8;
            cp_async16(Kb + r * HS + ch * 8, src + C_);
            cp_async16(Vb + r * HS + ch * 8, src + 2 * C_);
        }
        cp_commit();
    };

    float accO[8][4];
    #pragma unroll
    for (int ni = 0; ni < 8; ni++)
        #pragma unroll
        for (int r = 0; r < 4; r++) accO[ni][r] = 0.f;
    float m0 = -INFINITY, m1 = -INFINITY, l0 = 0.f, l1 = 0.f;

    int buf = 0;
    for (int kt = 0; kt <= qt; kt++) {
        if (kt < qt) { load_kv(kt + 1, buf ^ 1); cp_wait<1>(); }
        else         { cp_wait<0>(); }
        __syncthreads();

        const uint32_t kbase = (uint32_t)__cvta_generic_to_shared(Ks + buf * KVH);
        const uint32_t vbase = (uint32_t)__cvta_generic_to_shared(Vs + buf * KVH);

        // ---- S = Q K^T  (K B-frags via non-trans ldmatrix.x4, 2 ni/call) ----
        float accS[8][4];
        #pragma unroll
        for (int ni = 0; ni < 8; ni++)
            #pragma unroll
            for (int r = 0; r < 4; r++) accS[ni][r] = 0.f;

        #pragma unroll
        for (int s = 0; s < 4; s++) {
            const int kc = s * 16;
            #pragma unroll
            for (int np = 0; np < 4; np++) {
                const int ni  = 2 * np;
                const int row = ni * 8 + ((mat & 2) ? 8 : 0) + rin;
                const int col = kc + ((mat & 1) ? 8 : 0);
                uint32_t b0, b1, b2, b3;
                ldmx4(b0, b1, b2, b3, kbase + (uint32_t)(row * HS + col) * 2);
                mma_f16(accS[ni][0], accS[ni][1], accS[ni][2], accS[ni][3],
                        qf[s][0], qf[s][1], qf[s][2], qf[s][3], b0, b1);
                mma_f16(accS[ni+1][0], accS[ni+1][1], accS[ni+1][2], accS[ni+1][3],
                        qf[s][0], qf[s][1], qf[s][2], qf[s][3], b2, b3);
            }
        }

        // ---- log2-domain online softmax; pack P into A-fragments ----
        const bool diag = (kt == qt);
        float mx0 = -INFINITY, mx1 = -INFINITY;
        #pragma unroll
        for (int ni = 0; ni < 8; ni++) {
            float s0 = accS[ni][0] * SCALE_L2E;
            float s1 = accS[ni][1] * SCALE_L2E;
            float s2 = accS[ni][2] * SCALE_L2E;
            float s3 = accS[ni][3] * SCALE_L2E;
            if (diag) {
                const int j = ni * 8 + 2 * fc;
                if (j     > rlo    ) s0 = -INFINITY;
                if (j + 1 > rlo    ) s1 = -INFINITY;
                if (j     > rlo + 8) s2 = -INFINITY;
                if (j + 1 > rlo + 8) s3 = -INFINITY;
            }
            accS[ni][0] = s0; accS[ni][1] = s1;
            accS[ni][2] = s2; accS[ni][3] = s3;
            mx0 = fmaxf(mx0, fmaxf(s0, s1));
            mx1 = fmaxf(mx1, fmaxf(s2, s3));
        }
        mx0 = fmaxf(mx0, __shfl_xor_sync(0xffffffffu, mx0, 1));
        mx0 = fmaxf(mx0, __shfl_xor_sync(0xffffffffu, mx0, 2));
        mx1 = fmaxf(mx1, __shfl_xor_sync(0xffffffffu, mx1, 1));
        mx1 = fmaxf(mx1, __shfl_xor_sync(0xffffffffu, mx1, 2));

        const float mn0 = fmaxf(m0, mx0);
        const float mn1 = fmaxf(m1, mx1);
        const float c0 = exp2f(m0 - mn0);
        const float c1 = exp2f(m1 - mn1);

        uint32_t paf[8][2];
        float ls0 = 0.f, ls1 = 0.f;
        #pragma unroll
        for (int ni = 0; ni < 8; ni++) {
            const float p0 = exp2f(accS[ni][0] - mn0);
            const float p1 = exp2f(accS[ni][1] - mn0);
            const float p2 = exp2f(accS[ni][2] - mn1);
            const float p3 = exp2f(accS[ni][3] - mn1);
            ls0 += p0 + p1;  ls1 += p2 + p3;
            accO[ni][0] *= c0; accO[ni][1] *= c0;
            accO[ni][2] *= c1; accO[ni][3] *= c1;
            paf[ni][0] = packh2(p0, p1);
            paf[ni][1] = packh2(p2, p3);
        }
        ls0 += __shfl_xor_sync(0xffffffffu, ls0, 1);
        ls0 += __shfl_xor_sync(0xffffffffu, ls0, 2);
        ls1 += __shfl_xor_sync(0xffffffffu, ls1, 1);
        ls1 += __shfl_xor_sync(0xffffffffu, ls1, 2);
        l0 = l0 * c0 + ls0;
        l1 = l1 * c1 + ls1;
        m0 = mn0; m1 = mn1;

        // ---- O += P V  (P from regs; V via ldmatrix.trans) ----
        #pragma unroll
        for (int s = 0; s < 4; s++) {
            const int kc = s * 16;
            const uint32_t a0 = paf[2*s    ][0];
            const uint32_t a1 = paf[2*s    ][1];
            const uint32_t a2 = paf[2*s + 1][0];
            const uint32_t a3 = paf[2*s + 1][1];
            #pragma unroll
            for (int np = 0; np < 4; np++) {
                const int ni  = 2 * np;
                const int row = kc + ((mat & 1) ? 8 : 0) + rin;
                const int col = ni * 8 + ((mat & 2) ? 8 : 0);
                uint32_t b0, b1, b2, b3;
                ldmx4t(b0, b1, b2, b3, vbase + (uint32_t)(row * HS + col) * 2);
                mma_f16(accO[ni][0], accO[ni][1], accO[ni][2], accO[ni][3],
                        a0, a1, a2, a3, b0, b1);
                mma_f16(accO[ni+1][0], accO[ni+1][1], accO[ni+1][2], accO[ni+1][3],
                        a0, a1, a2, a3, b2, b3);
            }
        }

        __syncthreads();
        buf ^= 1;
    }

    const float inv0 = 1.f / l0;
    const float inv1 = 1.f / l1;
    const size_t grow = (size_t)(b * T_ + qt * 64 + rlo);
    #pragma unroll
    for (int ni = 0; ni < 8; ni++) {
        const int col = h * D_ + ni * 8 + 2 * fc;
        *(uint32_t*)(y + grow * C_ + col) =
            packh2(accO[ni][0] * inv0, accO[ni][1] * inv0);
        *(uint32_t*)(y + (grow + 8) * C_ + col) =
            packh2(accO[ni][2] * inv1, accO[ni][3] * inv1);
    }
}

// ---------------------------------------------------------------------------
// Launch
// ---------------------------------------------------------------------------
extern "C" void kernel_launch(void* const* d_in, const int* in_sizes, int n_in,
                              void* d_out, int out_size)
{
    (void)in_sizes; (void)n_in; (void)out_size;
    const float* x     = (const float*)d_in[0];
    const float* ln1_w = (const float*)d_in[1];
    const float* ln1_b = (const float*)d_in[2];
    const float* w_qkv = (const float*)d_in[3];
    const float* b_qkv = (const float*)d_in[4];
    const float* w_o   = (const float*)d_in[5];
    const float* b_o   = (const float*)d_in[6];
    const float* ln2_w = (const float*)d_in[7];
    const float* ln2_b = (const float*)d_in[8];
    const float* w_fc  = (const float*)d_in[9];
    const float* b_fc  = (const float*)d_in[10];
    const float* w_out = (const float*)d_in[11];
    const float* b_out = (const float*)d_in[12];
    float* out = (float*)d_out;

    __half *xn, *qkv, *y, *hbuf, *wq, *wo, *wf, *wu;
    float *x1;
    cudaGetSymbolAddress((void**)&xn,   g_xn);
    cudaGetSymbolAddress((void**)&qkv,  g_qkv);
    cudaGetSymbolAddress((void**)&y,    g_y);
    cudaGetSymbolAddress((void**)&x1,   g_x1);
    cudaGetSymbolAddress((void**)&hbuf, g_h);
    cudaGetSymbolAddress((void**)&wq,   g_wqkv);
    cudaGetSymbolAddress((void**)&wo,   g_wo);
    cudaGetSymbolAddress((void**)&wf,   g_wfc);
    cudaGetSymbolAddress((void**)&wu,   g_wout);

    cudaFuncSetAttribute(gemm_h_kernel<0,0,2>,
        cudaFuncAttributeMaxDynamicSharedMemorySize, SMEM_BYTES);
    cudaFuncSetAttribute(gemm_h_kernel<0,1,0>,
        cudaFuncAttributeMaxDynamicSharedMemorySize, SMEM_BYTES);
    cudaFuncSetAttribute(gemm_h_kernel<1,0,2>,
        cudaFuncAttributeMaxDynamicSharedMemorySize, SMEM_BYTES);
    cudaFuncSetAttribute(attn_h_kernel,
        cudaFuncAttributeMaxDynamicSharedMemorySize, ATTN_SMEM_BYTES);

    // 0) fused weight prep (all 4 weights, one launch)
    wprep_all_kernel<<<WCH3 / 512, 256>>>(
        w_qkv, wq, w_o, wo, w_fc, wf, w_out, wu);

    // 1) LN1 -> fp16
    ln_kernel<<<M_ / 8, 256>>>(x, ln1_w, ln1_b, xn);
    // 2) qkv = xn @ w_qkv + b_qkv  -> fp16
    gemm_h_kernel<0,0,2><<<dim3(3 * C_ / BN, M_ / BM), 256, SMEM_BYTES>>>(
        xn, wq, b_qkv, nullptr, qkv, M_, 3 * C_, C_);
    // 3) causal attention (fp16) -> y (fp16)
    attn_h_kernel<<<dim3(T_ / 64, H_, B_), 128, ATTN_SMEM_BYTES>>>(qkv, y);
    // 4) x1 = x + y @ w_o + b_o (fp32)
    gemm_h_kernel<0,1,0><<<dim3(C_ / BN, M_ / BM), 256, SMEM_BYTES>>>(
        y, wo, b_o, x, x1, M_, C_, C_);
    // 5) LN2 -> fp16
    ln_kernel<<<M_ / 8, 256>>>(x1, ln2_w, ln2_b, xn);
    // 6) h = gelu(xn @ w_fc + b_fc) -> fp16
    gemm_h_kernel<1,0,2><<<dim3(FF_ / BN, M_ / BM), 256, SMEM_BYTES>>>(
        xn, wf, b_fc, nullptr, hbuf, M_, FF_, C_);
    // 7) out = x1 + h @ w_out + b_out (fp32)
    gemm_h_kernel<0,1,0><<<dim3(C_ / BN, M_ / BM), 256, SMEM_BYTES>>>(
        hbuf, wu, b_out, x1, out, M_, C_, FF_);
}

// round 15
// speedup vs baseline: 1.0431x; 1.0202x over previous
#include <cuda_runtime.h>
#include <cuda_fp16.h>
#include <math.h>
#include <stdint.h>

// Problem constants
#define B_  4
#define T_  2048
#define H_  16
#define D_  64
#define C_  1024
#define FF_ 4096
#define M_  (B_ * T_)   // 8192 rows

// ---------------------------------------------------------------------------
// Scratch (device globals — no runtime allocation allowed)
// ---------------------------------------------------------------------------
__device__ __half g_xn  [M_ * C_];
__device__ __half g_qkv [M_ * 3 * C_];
__device__ __half g_y   [M_ * C_];
__device__ float  g_x1  [M_ * C_];
__device__ __half g_h   [M_ * FF_];
__device__ __half g_wqkv[C_ * 3 * C_];
__device__ __half g_wo  [C_ * C_];
__device__ __half g_wfc [C_ * FF_];
__device__ __half g_wout[FF_ * C_];

// ---------------------------------------------------------------------------
// Helpers
// ---------------------------------------------------------------------------
__device__ __forceinline__ uint32_t f2tf32(float f) {
    uint32_t r;
    asm("cvt.rna.tf32.f32 %0, %1;" : "=r"(r) : "f"(f));
    return r;
}
__device__ __forceinline__ float tf32_round(float f) {
    return __uint_as_float(f2tf32(f));
}

__device__ __forceinline__ void mma_f16(
    float& d0, float& d1, float& d2, float& d3,
    uint32_t a0, uint32_t a1, uint32_t a2, uint32_t a3,
    uint32_t b0, uint32_t b1)
{
    asm volatile(
        "mma.sync.aligned.m16n8k16.row.col.f32.f16.f16.f32 "
        "{%0,%1,%2,%3}, {%4,%5,%6,%7}, {%8,%9}, {%0,%1,%2,%3};\n"
        : "+f"(d0), "+f"(d1), "+f"(d2), "+f"(d3)
        : "r"(a0), "r"(a1), "r"(a2), "r"(a3), "r"(b0), "r"(b1));
}

__device__ __forceinline__ void ldmx4(
    uint32_t& d0, uint32_t& d1, uint32_t& d2, uint32_t& d3, uint32_t addr)
{
    asm volatile(
        "ldmatrix.sync.aligned.m8n8.x4.shared.b16 {%0,%1,%2,%3}, [%4];"
        : "=r"(d0), "=r"(d1), "=r"(d2), "=r"(d3) : "r"(addr));
}
__device__ __forceinline__ void ldmx4t(
    uint32_t& d0, uint32_t& d1, uint32_t& d2, uint32_t& d3, uint32_t addr)
{
    asm volatile(
        "ldmatrix.sync.aligned.m8n8.x4.trans.shared.b16 {%0,%1,%2,%3}, [%4];"
        : "=r"(d0), "=r"(d1), "=r"(d2), "=r"(d3) : "r"(addr));
}

__device__ __forceinline__ void cp_async16(void* dst_smem, const void* src) {
    uint32_t d = (uint32_t)__cvta_generic_to_shared(dst_smem);
    asm volatile("cp.async.cg.shared.global [%0], [%1], 16;\n" :: "r"(d), "l"(src));
}
__device__ __forceinline__ void cp_commit() {
    asm volatile("cp.async.commit_group;\n");
}
template<int N>
__device__ __forceinline__ void cp_wait() {
    asm volatile("cp.async.wait_group %0;\n" :: "n"(N));
}

__device__ __forceinline__ float gelu_exact(float x) {
    return 0.5f * x * (1.0f + erff(x * 0.70710678118654752f));
}
__device__ __forceinline__ uint32_t packh2(float a, float b) {
    __half2 h = __floats2half2_rn(a, b);
    return *(uint32_t*)&h;
}
__device__ __forceinline__ uint32_t ex2_h2(uint32_t x) {
    uint32_t r;
    asm("ex2.approx.f16x2 %0, %1;" : "=r"(r) : "r"(x));
    return r;
}

// ---------------------------------------------------------------------------
// Fused weight prep: all 4 weights, fp32 [K][N] -> fp16 interleaved
// ---------------------------------------------------------------------------
__device__ __forceinline__ void wprep_chunk(
    const float* __restrict__ src, __half* __restrict__ dst, int N, int idx)
{
    const int nq = N >> 2;
    const int kp = idx / nq;
    const int n4 = idx - kp * nq;
    const float4 r0 = *(const float4*)(src + (size_t)(2 * kp)     * N + 4 * n4);
    const float4 r1 = *(const float4*)(src + (size_t)(2 * kp + 1) * N + 4 * n4);
    __half2* d = (__half2*)(dst + (size_t)kp * (2 * N) + 8 * n4);
    d[0] = __halves2half2(__float2half_rn(r0.x), __float2half_rn(r1.x));
    d[1] = __halves2half2(__float2half_rn(r0.y), __float2half_rn(r1.y));
    d[2] = __halves2half2(__float2half_rn(r0.z), __float2half_rn(r1.z));
    d[3] = __halves2half2(__float2half_rn(r0.w), __float2half_rn(r1.w));
}

#define WCH0 393216
#define WCH1 (WCH0 + 131072)
#define WCH2 (WCH1 + 524288)
#define WCH3 (WCH2 + 524288)

__global__ void __launch_bounds__(256) wprep_all_kernel(
    const float* __restrict__ s0, __half* __restrict__ d0,
    const float* __restrict__ s1, __half* __restrict__ d1,
    const float* __restrict__ s2, __half* __restrict__ d2,
    const float* __restrict__ s3, __half* __restrict__ d3)
{
    #pragma unroll
    for (int u = 0; u < 2; u++) {
        const int g = (blockIdx.x * 2 + u) * 256 + threadIdx.x;
        if (g >= WCH3) return;
        if      (g < WCH0) wprep_chunk(s0, d0, 3 * C_, g);
        else if (g < WCH1) wprep_chunk(s1, d1, C_,     g - WCH0);
        else if (g < WCH2) wprep_chunk(s2, d2, FF_,    g - WCH1);
        else               wprep_chunk(s3, d3, C_,     g - WCH2);
    }
}

// ---------------------------------------------------------------------------
// LayerNorm: warp-per-row, pure shuffle reduction. Outputs fp16.
// ---------------------------------------------------------------------------
__global__ void __launch_bounds__(256) ln_kernel(
    const float* __restrict__ x, const float* __restrict__ w,
    const float* __restrict__ b, __half* __restrict__ out)
{
    const int lane = threadIdx.x & 31;
    const int row  = blockIdx.x * 8 + (threadIdx.x >> 5);
    const float4* xp = (const float4*)(x + (size_t)row * C_);

    float4 v[8];
    float s = 0.f, s2 = 0.f;
    #pragma unroll
    for (int i = 0; i < 8; i++) {
        v[i] = xp[lane + 32 * i];
        s  += v[i].x + v[i].y + v[i].z + v[i].w;
        s2 += v[i].x*v[i].x + v[i].y*v[i].y + v[i].z*v[i].z + v[i].w*v[i].w;
    }
    #pragma unroll
    for (int o = 16; o > 0; o >>= 1) {
        s  += __shfl_xor_sync(0xffffffffu, s,  o);
        s2 += __shfl_xor_sync(0xffffffffu, s2, o);
    }
    const float mean = s * (1.0f / C_);
    const float var  = s2 * (1.0f / C_) - mean * mean;
    const float rstd = rsqrtf(var + 1e-5f);

    uint2* op = (uint2*)(out + (size_t)row * C_);
    #pragma unroll
    for (int i = 0; i < 8; i++) {
        const float4 wv = ((const float4*)w)[lane + 32 * i];
        const float4 bv = ((const float4*)b)[lane + 32 * i];
        uint2 u;
        u.x = packh2((v[i].x - mean) * rstd * wv.x + bv.x,
                     (v[i].y - mean) * rstd * wv.y + bv.y);
        u.y = packh2((v[i].z - mean) * rstd * wv.z + bv.z,
                     (v[i].w - mean) * rstd * wv.w + bv.w);
        op[lane + 32 * i] = u;
    }
}

// ---------------------------------------------------------------------------
// FP16 tensor-core GEMM (proven kernel, f32 accumulators, BN=128).
// ---------------------------------------------------------------------------
#define BM 128
#define BN 128
#define BK 32
#define STAGES 3
#define A_STR 40
#define B_STR 272
#define A_TILE_H (BM * A_STR)
#define B_TILE_H (16 * B_STR)
#define SMEM_BYTES (STAGES * (A_TILE_H + B_TILE_H) * 2)   // 56832

template<int ACT, int RES, int OUT>
__global__ void __launch_bounds__(256) gemm_h_kernel(
    const __half* __restrict__ A, const __half* __restrict__ Wp,
    const float* __restrict__ bias, const float* __restrict__ res,
    void* __restrict__ outv, int M, int N, int K)
{
    extern __shared__ __half hsm[];
    __half* As = hsm;
    __half* Bs = hsm + STAGES * A_TILE_H;

    const int tid  = threadIdx.x;
    const int lane = tid & 31;
    const int wid  = tid >> 5;
    const int wm   = wid >> 2;
    const int wn   = wid & 3;
    const int bm   = blockIdx.y;
    const int bn   = blockIdx.x;
    const int fr   = lane >> 2;
    const int fc   = lane & 3;

    float acc[4][4][4];
    #pragma unroll
    for (int i = 0; i < 4; i++)
        #pragma unroll
        for (int j = 0; j < 4; j++)
            #pragma unroll
            for (int r = 0; r < 4; r++) acc[i][j][r] = 0.f;

    const int ntiles = K / BK;

    auto load_tile = [&](int t, int stg) {
        const int k0 = t * BK;
        __half* Ab = As + stg * A_TILE_H;
        __half* Bb = Bs + stg * B_TILE_H;
        #pragma unroll
        for (int i = 0; i < 2; i++) {
            const int idx = i * 256 + tid;
            const int row = idx >> 2, c4 = idx & 3;
            cp_async16(Ab + row * A_STR + c4 * 8,
                       A + (size_t)(bm * BM + row) * K + k0 + c4 * 8);
        }
        const int kp0 = k0 >> 1;
        #pragma unroll
        for (int i = 0; i < 2; i++) {
            const int idx = i * 256 + tid;
            const int kp = idx >> 5, ch = idx & 31;
            cp_async16(Bb + kp * B_STR + ch * 8,
                       Wp + (size_t)(kp0 + kp) * (2 * N) + (size_t)bn * (2 * BN) + ch * 8);
        }
        cp_commit();
    };

    load_tile(0, 0);
    load_tile(1, 1);

    for (int t = 0; t < ntiles; t++) {
        if (t + 2 < ntiles) load_tile(t + 2, (t + 2) % STAGES);
        else                cp_commit();
        cp_wait<2>();
        __syncthreads();

        const __half* Ab = As + (t % STAGES) * A_TILE_H;
        const __half* Bb = Bs + (t % STAGES) * B_TILE_H;

        #pragma unroll
        for (int ks = 0; ks < 2; ks++) {
            const int kc = ks * 16;
            uint32_t af[4][4], bf[4][2];
            #pragma unroll
            for (int mi = 0; mi < 4; mi++) {
                const int base = (wm * 64 + mi * 16 + fr) * A_STR + kc + 2 * fc;
                af[mi][0] = *(const uint32_t*)&Ab[base];
                af[mi][1] = *(const uint32_t*)&Ab[base + 8 * A_STR];
                af[mi][2] = *(const uint32_t*)&Ab[base + 8];
                af[mi][3] = *(const uint32_t*)&Ab[base + 8 * A_STR + 8];
            }
            const int kp = ks * 8 + fc;
            #pragma unroll
            for (int ni = 0; ni < 4; ni++) {
                const int n2 = 2 * (wn * 32 + ni * 8 + fr);
                bf[ni][0] = *(const uint32_t*)&Bb[kp * B_STR + n2];
                bf[ni][1] = *(const uint32_t*)&Bb[(kp + 4) * B_STR + n2];
            }
            #pragma unroll
            for (int mi = 0; mi < 4; mi++)
                #pragma unroll
                for (int ni = 0; ni < 4; ni++)
                    mma_f16(acc[mi][ni][0], acc[mi][ni][1],
                            acc[mi][ni][2], acc[mi][ni][3],
                            af[mi][0], af[mi][1], af[mi][2], af[mi][3],
                            bf[ni][0], bf[ni][1]);
        }
        __syncthreads();
    }

    #pragma unroll
    for (int mi = 0; mi < 4; mi++) {
        const int row0 = bm * BM + wm * 64 + mi * 16 + fr;
        #pragma unroll
        for (int ni = 0; ni < 4; ni++) {
            const int col = bn * BN + wn * 32 + ni * 8 + fc * 2;
            const float b0 = bias[col], b1 = bias[col + 1];

            float v0 = acc[mi][ni][0] + b0;
            float v1 = acc[mi][ni][1] + b1;
            float v2 = acc[mi][ni][2] + b0;
            float v3 = acc[mi][ni][3] + b1;
            if (ACT == 1) {
                v0 = gelu_exact(v0); v1 = gelu_exact(v1);
                v2 = gelu_exact(v2); v3 = gelu_exact(v3);
            }
            if (RES) {
                const float2 r0 = *(const float2*)(res + (size_t)row0 * N + col);
                const float2 r1 = *(const float2*)(res + (size_t)(row0 + 8) * N + col);
                v0 += r0.x; v1 += r0.y; v2 += r1.x; v3 += r1.y;
            }
            if (OUT == 2) {
                __half* out = (__half*)outv;
                *(uint32_t*)(out + (size_t)row0 * N + col)       = packh2(v0, v1);
                *(uint32_t*)(out + (size_t)(row0 + 8) * N + col) = packh2(v2, v3);
            } else {
                if (OUT == 1) {
                    v0 = tf32_round(v0); v1 = tf32_round(v1);
                    v2 = tf32_round(v2); v3 = tf32_round(v3);
                }
                float* out = (float*)outv;
                *(float2*)(out + (size_t)row0 * N + col)       = make_float2(v0, v1);
                *(float2*)(out + (size_t)(row0 + 8) * N + col) = make_float2(v2, v3);
            }
        }
    }
}

// ---------------------------------------------------------------------------
// FP16 causal flash attention: register-resident Q/P, ldmatrix K/V,
// log2-domain softmax with ex2.approx.f16x2 (P produced directly as the
// PV A-fragment half2 pairs; l summed in fp32 from the same f16 values).
// ---------------------------------------------------------------------------
#define HS 72
#define KVH (64 * HS)
#define ATTN_SMEM_BYTES (4 * KVH * 2)   // 2K + 2V = 36864 B
#define SCALE_L2E 0.18033688011112042f  // 0.125 * log2(e)

__global__ void __launch_bounds__(128, 5) attn_h_kernel(
    const __half* __restrict__ qkv, __half* __restrict__ y)
{
    extern __shared__ __half asm_[];
    __half* Ks = asm_;             // 2 buffers
    __half* Vs = Ks + 2 * KVH;     // 2 buffers

    const int qt   = (int)(gridDim.x - 1 - blockIdx.x);   // heavy tiles first
    const int h    = blockIdx.y;
    const int b    = blockIdx.z;
    const int tid  = threadIdx.x;
    const int lane = tid & 31;
    const int w    = tid >> 5;
    const int fr   = lane >> 2;
    const int fc   = lane & 3;
    const int mat  = lane >> 3;
    const int rin  = lane & 7;

    const size_t base = (size_t)(b * T_) * (3 * C_) + h * D_;
    const int rlo = w * 16 + fr;

    // ---- Q into registers (A-fragment layout), plus first K/V tile ----
    uint32_t qf[4][4];
    {
        const __half* q0 = qkv + base + (size_t)(qt * 64 + rlo) * (3 * C_);
        const __half* q1 = q0 + 8 * (3 * C_);
        #pragma unroll
        for (int s = 0; s < 4; s++) {
            const int kc = s * 16 + 2 * fc;
            qf[s][0] = *(const uint32_t*)&q0[kc];
            qf[s][1] = *(const uint32_t*)&q1[kc];
            qf[s][2] = *(const uint32_t*)&q0[kc + 8];
            qf[s][3] = *(const uint32_t*)&q1[kc + 8];
        }
        #pragma unroll
        for (int i = 0; i < 4; i++) {
            const int idx = i * 128 + tid;
            const int r = idx >> 3, ch = idx & 7;
            const __half* src = qkv + base + (size_t)r * (3 * C_) + ch * 8;
            cp_async16(Ks + r * HS + ch * 8, src + C_);
            cp_async16(Vs + r * HS + ch * 8, src + 2 * C_);
        }
        cp_commit();
    }

    auto load_kv = [&](int kt, int bufi) {
        __half* Kb = Ks + bufi * KVH;
        __half* Vb = Vs + bufi * KVH;
        #pragma unroll
        for (int i = 0; i < 4; i++) {
            const int idx = i * 128 + tid;
            const int r = idx >> 3, ch = idx & 7;
            const __half* src = qkv + base + (size_t)(kt * 64 + r) * (3 * C_) + ch * 8;
            cp_async16(Kb + r * HS + ch * 8, src + C_);
            cp_async16(Vb + r * HS + ch * 8, src + 2 * C_);
        }
        cp_commit();
    };

    float accO[8][4];
    #pragma unroll
    for (int ni = 0; ni < 8; ni++)
        #pragma unroll
        for (int r = 0; r < 4; r++) accO[ni][r] = 0.f;
    float m0 = -INFINITY, m1 = -INFINITY, l0 = 0.f, l1 = 0.f;

    int buf = 0;
    for (int kt = 0; kt <= qt; kt++) {
        if (kt < qt) { load_kv(kt + 1, buf ^ 1); cp_wait<1>(); }
        else         { cp_wait<0>(); }
        __syncthreads();

        const uint32_t kbase = (uint32_t)__cvta_generic_to_shared(Ks + buf * KVH);
        const uint32_t vbase = (uint32_t)__cvta_generic_to_shared(Vs + buf * KVH);

        // ---- S = Q K^T ----
        float accS[8][4];
        #pragma unroll
        for (int ni = 0; ni < 8; ni++)
            #pragma unroll
            for (int r = 0; r < 4; r++) accS[ni][r] = 0.f;

        #pragma unroll
        for (int s = 0; s < 4; s++) {
            const int kc = s * 16;
            #pragma unroll
            for (int np = 0; np < 4; np++) {
                const int ni  = 2 * np;
                const int row = ni * 8 + ((mat & 2) ? 8 : 0) + rin;
                const int col = kc + ((mat & 1) ? 8 : 0);
                uint32_t b0, b1, b2, b3;
                ldmx4(b0, b1, b2, b3, kbase + (uint32_t)(row * HS + col) * 2);
                mma_f16(accS[ni][0], accS[ni][1], accS[ni][2], accS[ni][3],
                        qf[s][0], qf[s][1], qf[s][2], qf[s][3], b0, b1);
                mma_f16(accS[ni+1][0], accS[ni+1][1], accS[ni+1][2], accS[ni+1][3],
                        qf[s][0], qf[s][1], qf[s][2], qf[s][3], b2, b3);
            }
        }

        // ---- log2-domain online softmax; ex2.f16x2 -> P A-fragments ----
        const bool diag = (kt == qt);
        float mx0 = -INFINITY, mx1 = -INFINITY;
        #pragma unroll
        for (int ni = 0; ni < 8; ni++) {
            float s0 = accS[ni][0] * SCALE_L2E;
            float s1 = accS[ni][1] * SCALE_L2E;
            float s2 = accS[ni][2] * SCALE_L2E;
            float s3 = accS[ni][3] * SCALE_L2E;
            if (diag) {
                const int j = ni * 8 + 2 * fc;
                if (j     > rlo    ) s0 = -INFINITY;
                if (j + 1 > rlo    ) s1 = -INFINITY;
                if (j     > rlo + 8) s2 = -INFINITY;
                if (j + 1 > rlo + 8) s3 = -INFINITY;
            }
            accS[ni][0] = s0; accS[ni][1] = s1;
            accS[ni][2] = s2; accS[ni][3] = s3;
            mx0 = fmaxf(mx0, fmaxf(s0, s1));
            mx1 = fmaxf(mx1, fmaxf(s2, s3));
        }
        mx0 = fmaxf(mx0, __shfl_xor_sync(0xffffffffu, mx0, 1));
        mx0 = fmaxf(mx0, __shfl_xor_sync(0xffffffffu, mx0, 2));
        mx1 = fmaxf(mx1, __shfl_xor_sync(0xffffffffu, mx1, 1));
        mx1 = fmaxf(mx1, __shfl_xor_sync(0xffffffffu, mx1, 2));

        const float mn0 = fmaxf(m0, mx0);
        const float mn1 = fmaxf(m1, mx1);
        const float c0 = exp2f(m0 - mn0);
        const float c1 = exp2f(m1 - mn1);

        uint32_t paf[8][2];
        float ls0 = 0.f, ls1 = 0.f;
        #pragma unroll
        for (int ni = 0; ni < 8; ni++) {
            const uint32_t p01 = ex2_h2(packh2(accS[ni][0] - mn0,
                                               accS[ni][1] - mn0));
            const uint32_t p23 = ex2_h2(packh2(accS[ni][2] - mn1,
                                               accS[ni][3] - mn1));
            paf[ni][0] = p01;
            paf[ni][1] = p23;
            const float2 f01 = __half22float2(*(const __half2*)&p01);
            const float2 f23 = __half22float2(*(const __half2*)&p23);
            ls0 += f01.x + f01.y;
            ls1 += f23.x + f23.y;
            accO[ni][0] *= c0; accO[ni][1] *= c0;
            accO[ni][2] *= c1; accO[ni][3] *= c1;
        }
        ls0 += __shfl_xor_sync(0xffffffffu, ls0, 1);
        ls0 += __shfl_xor_sync(0xffffffffu, ls0, 2);
        ls1 += __shfl_xor_sync(0xffffffffu, ls1, 1);
        ls1 += __shfl_xor_sync(0xffffffffu, ls1, 2);
        l0 = l0 * c0 + ls0;
        l1 = l1 * c1 + ls1;
        m0 = mn0; m1 = mn1;

        // ---- O += P V  (P from regs; V via ldmatrix.trans) ----
        #pragma unroll
        for (int s = 0; s < 4; s++) {
            const int kc = s * 16;
            const uint32_t a0 = paf[2*s    ][0];
            const uint32_t a1 = paf[2*s    ][1];
            const uint32_t a2 = paf[2*s + 1][0];
            const uint32_t a3 = paf[2*s + 1][1];
            #pragma unroll
            for (int np = 0; np < 4; np++) {
                const int ni  = 2 * np;
                const int row = kc + ((mat & 1) ? 8 : 0) + rin;
                const int col = ni * 8 + ((mat & 2) ? 8 : 0);
                uint32_t b0, b1, b2, b3;
                ldmx4t(b0, b1, b2, b3, vbase + (uint32_t)(row * HS + col) * 2);
                mma_f16(accO[ni][0], accO[ni][1], accO[ni][2], accO[ni][3],
                        a0, a1, a2, a3, b0, b1);
                mma_f16(accO[ni+1][0], accO[ni+1][1], accO[ni+1][2], accO[ni+1][3],
                        a0, a1, a2, a3, b2, b3);
            }
        }

        __syncthreads();
        buf ^= 1;
    }

    const float inv0 = 1.f / l0;
    const float inv1 = 1.f / l1;
    const size_t grow = (size_t)(b * T_ + qt * 64 + rlo);
    #pragma unroll
    for (int ni = 0; ni < 8; ni++) {
        const int col = h * D_ + ni * 8 + 2 * fc;
        *(uint32_t*)(y + grow * C_ + col) =
            packh2(accO[ni][0] * inv0, accO[ni][1] * inv0);
        *(uint32_t*)(y + (grow + 8) * C_ + col) =
            packh2(accO[ni][2] * inv1, accO[ni][3] * inv1);
    }
}

// ---------------------------------------------------------------------------
// Launch
// ---------------------------------------------------------------------------
extern "C" void kernel_launch(void* const* d_in, const int* in_sizes, int n_in,
                              void* d_out, int out_size)
{
    (void)in_sizes; (void)n_in; (void)out_size;
    const float* x     = (const float*)d_in[0];
    const float* ln1_w = (const float*)d_in[1];
    const float* ln1_b = (const float*)d_in[2];
    const float* w_qkv = (const float*)d_in[3];
    const float* b_qkv = (const float*)d_in[4];
    const float* w_o   = (const float*)d_in[5];
    const float* b_o   = (const float*)d_in[6];
    const float* ln2_w = (const float*)d_in[7];
    const float* ln2_b = (const float*)d_in[8];
    const float* w_fc  = (const float*)d_in[9];
    const float* b_fc  = (const float*)d_in[10];
    const float* w_out = (const float*)d_in[11];
    const float* b_out = (const float*)d_in[12];
    float* out = (float*)d_out;

    __half *xn, *qkv, *y, *hbuf, *wq, *wo, *wf, *wu;
    float *x1;
    cudaGetSymbolAddress((void**)&xn,   g_xn);
    cudaGetSymbolAddress((void**)&qkv,  g_qkv);
    cudaGetSymbolAddress((void**)&y,    g_y);
    cudaGetSymbolAddress((void**)&x1,   g_x1);
    cudaGetSymbolAddress((void**)&hbuf, g_h);
    cudaGetSymbolAddress((void**)&wq,   g_wqkv);
    cudaGetSymbolAddress((void**)&wo,   g_wo);
    cudaGetSymbolAddress((void**)&wf,   g_wfc);
    cudaGetSymbolAddress((void**)&wu,   g_wout);

    cudaFuncSetAttribute(gemm_h_kernel<0,0,2>,
        cudaFuncAttributeMaxDynamicSharedMemorySize, SMEM_BYTES);
    cudaFuncSetAttribute(gemm_h_kernel<0,1,0>,
        cudaFuncAttributeMaxDynamicSharedMemorySize, SMEM_BYTES);
    cudaFuncSetAttribute(gemm_h_kernel<1,0,2>,
        cudaFuncAttributeMaxDynamicSharedMemorySize, SMEM_BYTES);
    cudaFuncSetAttribute(attn_h_kernel,
        cudaFuncAttributeMaxDynamicSharedMemorySize, ATTN_SMEM_BYTES);

    // 0) fused weight prep (all 4 weights, one launch)
    wprep_all_kernel<<<WCH3 / 512, 256>>>(
        w_qkv, wq, w_o, wo, w_fc, wf, w_out, wu);

    // 1) LN1 -> fp16
    ln_kernel<<<M_ / 8, 256>>>(x, ln1_w, ln1_b, xn);
    // 2) qkv = xn @ w_qkv + b_qkv  -> fp16
    gemm_h_kernel<0,0,2><<<dim3(3 * C_ / BN, M_ / BM), 256, SMEM_BYTES>>>(
        xn, wq, b_qkv, nullptr, qkv, M_, 3 * C_, C_);
    // 3) causal attention (fp16) -> y (fp16)
    attn_h_kernel<<<dim3(T_ / 64, H_, B_), 128, ATTN_SMEM_BYTES>>>(qkv, y);
    // 4) x1 = x + y @ w_o + b_o (fp32)
    gemm_h_kernel<0,1,0><<<dim3(C_ / BN, M_ / BM), 256, SMEM_BYTES>>>(
        y, wo, b_o, x, x1, M_, C_, C_);
    // 5) LN2 -> fp16
    ln_kernel<<<M_ / 8, 256>>>(x1, ln2_w, ln2_b, xn);
    // 6) h = gelu(xn @ w_fc + b_fc) -> fp16
    gemm_h_kernel<1,0,2><<<dim3(FF_ / BN, M_ / BM), 256, SMEM_BYTES>>>(
        xn, wf, b_fc, nullptr, hbuf, M_, FF_, C_);
    // 7) out = x1 + h @ w_out + b_out (fp32)
    gemm_h_kernel<0,1,0><<<dim3(C_ / BN, M_ / BM), 256, SMEM_BYTES>>>(
        hbuf, wu, b_out, x1, out, M_, C_, FF_);
}